// round 5
// baseline (speedup 1.0000x reference)
#include <cuda_runtime.h>
#include <math.h>

#define HID 64
#define MAX_N 100000
#define MAX_E 1600000

// ---------------- device scratch (no allocations allowed) ----------------
// packed per-node gather row: [0:64)=node_proj, [64:128)=node_hidden (51.2MB)
__device__ float g_packed[MAX_N * 128];
__device__ float g_h_new[MAX_N * HID];       // 25.6 MB
// bf16 weight images, pre-swizzled into the smem tile layout:
// tile row stride 256B (128 bf16), 16B chunks, chunk c of row r stored at
// byte r*256 + ((c ^ (r&7))*16).
__device__ uint4 g_Wb_edge[64 * 16];         // W_edge  [j][k] bf16
__device__ uint4 g_Wb_node[64 * 16];         // W_node  [j][k] bf16
__device__ uint4 g_Wb_big[256 * 16];         // fused GRU weights [j][k] bf16

// ---------------- helpers -------------------------------------------------
__device__ __forceinline__ unsigned f2bf2(float lo, float hi) {
    unsigned r;
    asm("cvt.rn.bf16x2.f32 %0, %1, %2;" : "=r"(r) : "f"(hi), "f"(lo));
    return r;
}

__device__ __forceinline__ int swz(int row, int chunk) {
    return row * 256 + ((chunk ^ (row & 7)) << 4);
}

__device__ __forceinline__ void mma16816(float c[4],
                                         unsigned a0, unsigned a1,
                                         unsigned a2, unsigned a3,
                                         unsigned b0, unsigned b1) {
    asm("mma.sync.aligned.m16n8k16.row.col.f32.bf16.bf16.f32 "
        "{%0,%1,%2,%3},{%4,%5,%6,%7},{%8,%9},{%0,%1,%2,%3};"
        : "+f"(c[0]), "+f"(c[1]), "+f"(c[2]), "+f"(c[3])
        : "r"(a0), "r"(a1), "r"(a2), "r"(a3), "r"(b0), "r"(b1));
}

__device__ __forceinline__ void cp16(unsigned dst, const void* src) {
    asm volatile("cp.async.cg.shared.global [%0], [%1], 16;"
                 :: "r"(dst), "l"(src) : "memory");
}

// ---------------- weight prep: bf16 convert + swizzle + GRU fusion --------
// Fused GRU weight [j][k], j in [0,256), k in [0,128):
//   cols of G: [0:64)=r pre-act, [64:128)=z, [128:192)=gi_n, [192:256)=gh_n
__global__ void prep_kernel(const float* __restrict__ W_edge,
                            const float* __restrict__ W_node,
                            const float* __restrict__ W_ih,
                            const float* __restrict__ W_hh) {
    int idx = blockIdx.x * blockDim.x + threadIdx.x;  // one 16B chunk each
    float v[8];
    uint4* dst;
    if (idx < 1024) {
        int j = idx >> 4, c = idx & 15;
        const float* p = W_edge + j * 128 + c * 8;
#pragma unroll
        for (int i = 0; i < 8; i++) v[i] = p[i];
        dst = g_Wb_edge + (j * 16 + (c ^ (j & 7)));
    } else if (idx < 2048) {
        int i2 = idx - 1024;
        int j = i2 >> 4, c = i2 & 15;
        const float* p = W_node + j * 128 + c * 8;
#pragma unroll
        for (int i = 0; i < 8; i++) v[i] = p[i];
        dst = g_Wb_node + (j * 16 + (c ^ (j & 7)));
    } else if (idx < 6144) {
        int i3 = idx - 2048;
        int j = i3 >> 4, c = i3 & 15;
#pragma unroll
        for (int i = 0; i < 8; i++) {
            int k = c * 8 + i;
            float val = 0.f;
            if (k < 64) {
                if (j < 192) val = W_ih[j * 64 + k];
            } else {
                int kk = k - 64;
                if (j < 128)       val = W_hh[j * 64 + kk];
                else if (j >= 192) val = W_hh[(j - 64) * 64 + kk];
            }
            v[i] = val;
        }
        dst = g_Wb_big + (j * 16 + (c ^ (j & 7)));
    } else {
        return;
    }
    uint4 o;
    o.x = f2bf2(v[0], v[1]);
    o.y = f2bf2(v[2], v[3]);
    o.z = f2bf2(v[4], v[5]);
    o.w = f2bf2(v[6], v[7]);
    *dst = o;
}

// ---------------- node_proj + pack hidden + zero h_new --------------------
// Block: 128 rows. Also copies hidden into g_packed[:,64:128] and zeroes
// g_h_new for its rows (replaces the old init kernel).
__global__ void nodeproj_kernel(const float* __restrict__ nf,
                                const float* __restrict__ hidden, int N) {
    __shared__ __align__(16) char sm[49152];
    char* As = sm;                 // 128 x 256B bf16, swizzled
    char* Bs = sm + 32768;         // 64 x 256B bf16, swizzled
    float* Ms = (float*)sm;        // overlay [128][68] fp32 staging
    int t = threadIdx.x;
    int base = blockIdx.x * 128;

#pragma unroll
    for (int i = 0; i < 16; i++) {
        int idx = i * 256 + t;
        int row = idx >> 5, col4 = idx & 31;
        int r = base + row; if (r >= N) r = N - 1;
        float4 v = *(const float4*)(nf + (size_t)r * 128 + col4 * 4);
        unsigned p0 = f2bf2(v.x, v.y), p1 = f2bf2(v.z, v.w);
        *(uint2*)(As + swz(row, col4 >> 1) + (col4 & 1) * 8) = make_uint2(p0, p1);
    }
#pragma unroll
    for (int i = 0; i < 4; i++) ((uint4*)Bs)[i * 256 + t] = g_Wb_node[i * 256 + t];

    // hidden copy + h_new zero for this block's rows (independent of GEMM)
#pragma unroll
    for (int i = 0; i < 8; i++) {
        int idx = i * 256 + t;           // 2048 float4 chunks
        int row = idx >> 4, c4 = idx & 15;
        int r = base + row;
        if (r < N) {
            *(float4*)(g_packed + (size_t)r * 128 + 64 + c4 * 4) =
                *(const float4*)(hidden + (size_t)r * 64 + c4 * 4);
            *(float4*)(g_h_new + (size_t)r * 64 + c4 * 4) = make_float4(0.f, 0.f, 0.f, 0.f);
        }
    }
    __syncthreads();

    int lane = t & 31, w = t >> 5;
    int mr = w * 16;
    int qr = lane >> 2, qc = (lane & 3) * 4;
    float acc[8][4];
#pragma unroll
    for (int n = 0; n < 8; n++)
#pragma unroll
        for (int q = 0; q < 4; q++) acc[n][q] = 0.f;

#pragma unroll
    for (int k0 = 0; k0 < 128; k0 += 16) {
        int c0 = k0 >> 3, c1 = c0 + 1;
        unsigned a0 = *(unsigned*)(As + swz(mr + qr, c0) + qc);
        unsigned a1 = *(unsigned*)(As + swz(mr + qr + 8, c0) + qc);
        unsigned a2 = *(unsigned*)(As + swz(mr + qr, c1) + qc);
        unsigned a3 = *(unsigned*)(As + swz(mr + qr + 8, c1) + qc);
#pragma unroll
        for (int nt = 0; nt < 8; nt++) {
            unsigned b0 = *(unsigned*)(Bs + swz(nt * 8 + qr, c0) + qc);
            unsigned b1 = *(unsigned*)(Bs + swz(nt * 8 + qr, c1) + qc);
            mma16816(acc[nt], a0, a1, a2, a3, b0, b1);
        }
    }
    __syncthreads();
#pragma unroll
    for (int nt = 0; nt < 8; nt++) {
        int col = nt * 8 + (lane & 3) * 2;
        *(float2*)(Ms + (mr + qr) * 68 + col)     = make_float2(acc[nt][0], acc[nt][1]);
        *(float2*)(Ms + (mr + qr + 8) * 68 + col) = make_float2(acc[nt][2], acc[nt][3]);
    }
    __syncthreads();
#pragma unroll
    for (int i = 0; i < 8; i++) {
        int idx = i * 256 + t;
        int row = idx >> 4, c4 = idx & 15;
        int r = base + row;
        if (r < N)
            *(float4*)(g_packed + (size_t)r * 128 + c4 * 4) = *(float4*)(Ms + row * 68 + c4 * 4);
    }
}

// ---------------- fused edge kernel ---------------------------------------
// cp.async prefetch of gather rows overlaps the GEMM; phase 2 is smem-only.
// Dynamic smem: [0,48K) As+Bs / Ms overlay; [48K,112K) Gs gather rows.
__global__ void __launch_bounds__(256, 2)
edge_kernel(const float* __restrict__ ef,
            const int* __restrict__ src,
            const int* __restrict__ dst,
            int E) {
    extern __shared__ __align__(16) char dsm[];
    char* As = dsm;                 // 128 x 256B bf16
    char* Bs = dsm + 32768;         // 64 x 256B bf16
    float* Ms = (float*)dsm;        // overlay [128][68] fp32
    float* Gs = (float*)(dsm + 49152);  // [128][128] gathered packed rows
    int t = threadIdx.x;
    int lane = t & 31, w = t >> 5;
    int base = blockIdx.x * 128;

    // ---- phase 0: prefetch gather rows via cp.async (overlaps everything) --
    unsigned gs_base;
    {
        void* p = Gs + (size_t)(w * 16) * 128;
        gs_base = (unsigned)__cvta_generic_to_shared(p);
    }
    int eclamp = E - 1;
    int myidx = 0, myd = 0;
    {
        int ei = base + w * 16 + (lane & 15);
        if (ei > eclamp) ei = eclamp;
        if (lane < 16) {
            myidx = __ldg(src + ei);
            myd   = __ldg(dst + ei);
        }
    }
#pragma unroll
    for (int i = 0; i < 16; i++) {
        int s = __shfl_sync(0xffffffffu, myidx, i);
        const char* gp = (const char*)(g_packed + (size_t)s * 128) + lane * 16;
        cp16(gs_base + i * 512 + lane * 16, gp);
    }
    asm volatile("cp.async.commit_group;" ::: "memory");

    // ---- phase 1: A tile load + convert, B copy ----------------------------
#pragma unroll
    for (int i = 0; i < 16; i++) {
        int idx = i * 256 + t;
        int row = idx >> 5, col4 = idx & 31;
        int r = base + row; if (r >= E) r = E - 1;
        float4 v = *(const float4*)(ef + (size_t)r * 128 + col4 * 4);
        unsigned p0 = f2bf2(v.x, v.y), p1 = f2bf2(v.z, v.w);
        *(uint2*)(As + swz(row, col4 >> 1) + (col4 & 1) * 8) = make_uint2(p0, p1);
    }
#pragma unroll
    for (int i = 0; i < 4; i++) ((uint4*)Bs)[i * 256 + t] = g_Wb_edge[i * 256 + t];
    __syncthreads();

    // ---- GEMM --------------------------------------------------------------
    int mr = w * 16;
    int qr = lane >> 2, qc = (lane & 3) * 4;
    float acc[8][4];
#pragma unroll
    for (int n = 0; n < 8; n++)
#pragma unroll
        for (int q = 0; q < 4; q++) acc[n][q] = 0.f;

#pragma unroll
    for (int k0 = 0; k0 < 128; k0 += 16) {
        int c0 = k0 >> 3, c1 = c0 + 1;
        unsigned a0 = *(unsigned*)(As + swz(mr + qr, c0) + qc);
        unsigned a1 = *(unsigned*)(As + swz(mr + qr + 8, c0) + qc);
        unsigned a2 = *(unsigned*)(As + swz(mr + qr, c1) + qc);
        unsigned a3 = *(unsigned*)(As + swz(mr + qr + 8, c1) + qc);
#pragma unroll
        for (int nt = 0; nt < 8; nt++) {
            unsigned b0 = *(unsigned*)(Bs + swz(nt * 8 + qr, c0) + qc);
            unsigned b1 = *(unsigned*)(Bs + swz(nt * 8 + qr, c1) + qc);
            mma16816(acc[nt], a0, a1, a2, a3, b0, b1);
        }
    }
    __syncthreads();   // done reading As/Bs; overlay Ms
#pragma unroll
    for (int nt = 0; nt < 8; nt++) {
        int col = nt * 8 + (lane & 3) * 2;
        *(float2*)(Ms + (mr + qr) * 68 + col)     = make_float2(acc[nt][0], acc[nt][1]);
        *(float2*)(Ms + (mr + qr + 8) * 68 + col) = make_float2(acc[nt][2], acc[nt][3]);
    }
    asm volatile("cp.async.wait_group 0;" ::: "memory");
    __syncthreads();

    // ---- phase 2: half-warp per edge, all smem -----------------------------
    int half = lane >> 4;          // 0 or 1
    int hl = lane & 15;            // 0..15
#pragma unroll
    for (int i = 0; i < 8; i++) {
        int e = w * 16 + 2 * i + half;      // local edge of MY half
        int ge = base + e;
        int d = __shfl_sync(0xffffffffu, myd, 2 * i + half);
        float4 proj = *(float4*)(Gs + (size_t)e * 128 + hl * 4);
        float4 msg  = *(float4*)(Ms + (size_t)e * 68 + hl * 4);
        float v0 = proj.x + msg.x, v1 = proj.y + msg.y;
        float v2 = proj.z + msg.z, v3 = proj.w + msg.w;
        float mx = fmaxf(fmaxf(v0, v1), fmaxf(v2, v3));
#pragma unroll
        for (int o = 8; o > 0; o >>= 1)
            mx = fmaxf(mx, __shfl_xor_sync(0xffffffffu, mx, o));
        float e0 = __expf(v0 - mx), e1 = __expf(v1 - mx);
        float e2 = __expf(v2 - mx), e3 = __expf(v3 - mx);
        float ssum = (e0 + e1) + (e2 + e3);
#pragma unroll
        for (int o = 8; o > 0; o >>= 1)
            ssum += __shfl_xor_sync(0xffffffffu, ssum, o);
        float inv = 1.0f / ssum;
        float4 hid = *(float4*)(Gs + (size_t)e * 128 + 64 + hl * 4);
        float m0 = hid.x * e0 * inv, m1 = hid.y * e1 * inv;
        float m2 = hid.z * e2 * inv, m3 = hid.w * e3 * inv;
        if (ge < E) {
            float* addr = g_h_new + (size_t)d * 64 + hl * 4;
            asm volatile("red.global.add.v4.f32 [%0], {%1, %2, %3, %4};"
                         :: "l"(addr), "f"(m0), "f"(m1), "f"(m2), "f"(m3) : "memory");
        }
    }
}

// ---------------- GRU kernel (bf16 mma, fused 256-wide gate GEMM) ---------
__global__ void gru_kernel(const float* __restrict__ hidden,
                           const float* __restrict__ b_ih,
                           const float* __restrict__ b_hh,
                           float* __restrict__ out, int N) {
    extern __shared__ __align__(16) char dsm[];
    char* As = dsm;                // 64 x 256B
    char* Bs = dsm + 16384;        // 256 x 256B
    float* Gs = (float*)dsm;       // overlay [64][260]
    int t = threadIdx.x;
    int base = blockIdx.x * 64;

#pragma unroll
    for (int i = 0; i < 8; i++) {
        int idx = i * 256 + t;
        int row = idx >> 5, col4 = idx & 31;
        int r = base + row; if (r >= N) r = N - 1;
        const float* p = (col4 < 16) ? (g_h_new + (size_t)r * 64 + col4 * 4)
                                     : (hidden  + (size_t)r * 64 + (col4 - 16) * 4);
        float4 v = *(const float4*)p;
        unsigned p0 = f2bf2(v.x, v.y), p1 = f2bf2(v.z, v.w);
        *(uint2*)(As + swz(row, col4 >> 1) + (col4 & 1) * 8) = make_uint2(p0, p1);
    }
#pragma unroll
    for (int i = 0; i < 16; i++) ((uint4*)Bs)[i * 256 + t] = g_Wb_big[i * 256 + t];
    __syncthreads();

    int lane = t & 31, w = t >> 5;
    int mr = (w & 3) * 16;
    int ncb = (w >> 2) * 128;
    int qr = lane >> 2, qc = (lane & 3) * 4;
    float acc[16][4];
#pragma unroll
    for (int n = 0; n < 16; n++)
#pragma unroll
        for (int q = 0; q < 4; q++) acc[n][q] = 0.f;

#pragma unroll
    for (int k0 = 0; k0 < 128; k0 += 16) {
        int c0 = k0 >> 3, c1 = c0 + 1;
        unsigned a0 = *(unsigned*)(As + swz(mr + qr, c0) + qc);
        unsigned a1 = *(unsigned*)(As + swz(mr + qr + 8, c0) + qc);
        unsigned a2 = *(unsigned*)(As + swz(mr + qr, c1) + qc);
        unsigned a3 = *(unsigned*)(As + swz(mr + qr + 8, c1) + qc);
#pragma unroll
        for (int nt = 0; nt < 16; nt++) {
            unsigned b0 = *(unsigned*)(Bs + swz(ncb + nt * 8 + qr, c0) + qc);
            unsigned b1 = *(unsigned*)(Bs + swz(ncb + nt * 8 + qr, c1) + qc);
            mma16816(acc[nt], a0, a1, a2, a3, b0, b1);
        }
    }
    __syncthreads();
#pragma unroll
    for (int nt = 0; nt < 16; nt++) {
        int col = ncb + nt * 8 + (lane & 3) * 2;
        *(float2*)(Gs + (mr + qr) * 260 + col)     = make_float2(acc[nt][0], acc[nt][1]);
        *(float2*)(Gs + (mr + qr + 8) * 260 + col) = make_float2(acc[nt][2], acc[nt][3]);
    }
    __syncthreads();

    int row = t >> 2;                 // 0..63
    int jb = (t & 3) * 16;
    int gr_ = base + row;
    if (gr_ < N) {
#pragma unroll
        for (int jj = 0; jj < 16; jj++) {
            int j = jb + jj;
            float pr = Gs[row * 260 + j]       + b_ih[j]        + b_hh[j];
            float pz = Gs[row * 260 + 64 + j]  + b_ih[64 + j]   + b_hh[64 + j];
            float pi = Gs[row * 260 + 128 + j] + b_ih[128 + j];
            float ph = Gs[row * 260 + 192 + j] + b_hh[128 + j];
            float r = 1.0f / (1.0f + __expf(-pr));
            float z = 1.0f / (1.0f + __expf(-pz));
            float ng = tanhf(fmaf(r, ph, pi));
            float h = hidden[(size_t)gr_ * 64 + j];
            out[(size_t)gr_ * 64 + j] = fmaf(1.0f - z, ng, z * h);
        }
    }
}

// ---------------- launch --------------------------------------------------
extern "C" void kernel_launch(void* const* d_in, const int* in_sizes, int n_in,
                              void* d_out, int out_size) {
    const float* node_feats  = (const float*)d_in[0];
    const float* edge_feats  = (const float*)d_in[1];
    const float* node_hidden = (const float*)d_in[2];
    const int*   src         = (const int*)d_in[3];
    const int*   dst         = (const int*)d_in[4];
    const float* W_edge      = (const float*)d_in[5];
    const float* W_node      = (const float*)d_in[6];
    const float* W_ih        = (const float*)d_in[7];
    const float* W_hh        = (const float*)d_in[8];
    const float* b_ih        = (const float*)d_in[9];
    const float* b_hh        = (const float*)d_in[10];
    float* out = (float*)d_out;

    int E = in_sizes[3];
    int N = in_sizes[2] / HID;

    prep_kernel<<<24, 256>>>(W_edge, W_node, W_ih, W_hh);

    nodeproj_kernel<<<(N + 127) / 128, 256>>>(node_feats, node_hidden, N);

    static const int EDGE_SMEM = 49152 + 65536;   // 112 KB dynamic
    cudaFuncSetAttribute(edge_kernel, cudaFuncAttributeMaxDynamicSharedMemorySize, EDGE_SMEM);
    edge_kernel<<<(E + 127) / 128, 256, EDGE_SMEM>>>(edge_feats, src, dst, E);

    static const int GRU_SMEM = 16384 + 65536;    // 80 KB dynamic
    cudaFuncSetAttribute(gru_kernel, cudaFuncAttributeMaxDynamicSharedMemorySize, GRU_SMEM);
    gru_kernel<<<(N + 63) / 64, 256, GRU_SMEM>>>(node_hidden, b_ih, b_hh, out, N);
}

// round 8
// speedup vs baseline: 1.1478x; 1.1478x over previous
#include <cuda_runtime.h>
#include <math.h>

#define HID 64
#define MAX_N 100000
#define MAX_E 1600000

// ---------------- device scratch (no allocations allowed) ----------------
// packed per-node gather row: [0:64)=node_proj, [64:128)=node_hidden (51.2MB)
__device__ float g_packed[MAX_N * 128];
__device__ float g_h_new[MAX_N * HID];       // 25.6 MB
// bf16 weight images, pre-swizzled into the smem tile layout:
// tile row stride 256B (128 bf16), 16B chunks, chunk c of row r stored at
// byte r*256 + ((c ^ (r&7))*16).
__device__ uint4 g_Wb_edge[64 * 16];         // W_edge  [j][k] bf16
__device__ uint4 g_Wb_node[64 * 16];         // W_node  [j][k] bf16
__device__ uint4 g_Wb_big[256 * 16];         // fused GRU weights [j][k] bf16

// ---------------- helpers -------------------------------------------------
__device__ __forceinline__ unsigned f2bf2(float lo, float hi) {
    unsigned r;
    asm("cvt.rn.bf16x2.f32 %0, %1, %2;" : "=r"(r) : "f"(hi), "f"(lo));
    return r;
}

__device__ __forceinline__ int swz(int row, int chunk) {
    return row * 256 + ((chunk ^ (row & 7)) << 4);
}

__device__ __forceinline__ void mma16816(float c[4],
                                         unsigned a0, unsigned a1,
                                         unsigned a2, unsigned a3,
                                         unsigned b0, unsigned b1) {
    asm("mma.sync.aligned.m16n8k16.row.col.f32.bf16.bf16.f32 "
        "{%0,%1,%2,%3},{%4,%5,%6,%7},{%8,%9},{%0,%1,%2,%3};"
        : "+f"(c[0]), "+f"(c[1]), "+f"(c[2]), "+f"(c[3])
        : "r"(a0), "r"(a1), "r"(a2), "r"(a3), "r"(b0), "r"(b1));
}

// ---------------- weight prep: bf16 convert + swizzle + GRU fusion --------
// Fused GRU weight [j][k], j in [0,256), k in [0,128):
//   cols of G: [0:64)=r pre-act, [64:128)=z, [128:192)=gi_n, [192:256)=gh_n
__global__ void prep_kernel(const float* __restrict__ W_edge,
                            const float* __restrict__ W_node,
                            const float* __restrict__ W_ih,
                            const float* __restrict__ W_hh) {
    int idx = blockIdx.x * blockDim.x + threadIdx.x;  // one 16B chunk each
    float v[8];
    uint4* dst;
    if (idx < 1024) {
        int j = idx >> 4, c = idx & 15;
        const float* p = W_edge + j * 128 + c * 8;
#pragma unroll
        for (int i = 0; i < 8; i++) v[i] = p[i];
        dst = g_Wb_edge + (j * 16 + (c ^ (j & 7)));
    } else if (idx < 2048) {
        int i2 = idx - 1024;
        int j = i2 >> 4, c = i2 & 15;
        const float* p = W_node + j * 128 + c * 8;
#pragma unroll
        for (int i = 0; i < 8; i++) v[i] = p[i];
        dst = g_Wb_node + (j * 16 + (c ^ (j & 7)));
    } else if (idx < 6144) {
        int i3 = idx - 2048;
        int j = i3 >> 4, c = i3 & 15;
#pragma unroll
        for (int i = 0; i < 8; i++) {
            int k = c * 8 + i;
            float val = 0.f;
            if (k < 64) {
                if (j < 192) val = W_ih[j * 64 + k];
            } else {
                int kk = k - 64;
                if (j < 128)       val = W_hh[j * 64 + kk];
                else if (j >= 192) val = W_hh[(j - 64) * 64 + kk];
            }
            v[i] = val;
        }
        dst = g_Wb_big + (j * 16 + (c ^ (j & 7)));
    } else {
        return;
    }
    uint4 o;
    o.x = f2bf2(v[0], v[1]);
    o.y = f2bf2(v[2], v[3]);
    o.z = f2bf2(v[4], v[5]);
    o.w = f2bf2(v[6], v[7]);
    *dst = o;
}

// ---------------- node_proj + pack hidden + zero h_new --------------------
__global__ void nodeproj_kernel(const float* __restrict__ nf,
                                const float* __restrict__ hidden, int N) {
    __shared__ __align__(16) char sm[49152];
    char* As = sm;                 // 128 x 256B bf16, swizzled
    char* Bs = sm + 32768;         // 64 x 256B bf16, swizzled
    float* Ms = (float*)sm;        // overlay [128][68] fp32 staging
    int t = threadIdx.x;
    int base = blockIdx.x * 128;

#pragma unroll
    for (int i = 0; i < 16; i++) {
        int idx = i * 256 + t;
        int row = idx >> 5, col4 = idx & 31;
        int r = base + row; if (r >= N) r = N - 1;
        float4 v = *(const float4*)(nf + (size_t)r * 128 + col4 * 4);
        unsigned p0 = f2bf2(v.x, v.y), p1 = f2bf2(v.z, v.w);
        *(uint2*)(As + swz(row, col4 >> 1) + (col4 & 1) * 8) = make_uint2(p0, p1);
    }
#pragma unroll
    for (int i = 0; i < 4; i++) ((uint4*)Bs)[i * 256 + t] = g_Wb_node[i * 256 + t];

    // hidden copy + h_new zero for this block's rows (independent of GEMM)
#pragma unroll
    for (int i = 0; i < 8; i++) {
        int idx = i * 256 + t;           // 2048 float4 chunks
        int row = idx >> 4, c4 = idx & 15;
        int r = base + row;
        if (r < N) {
            *(float4*)(g_packed + (size_t)r * 128 + 64 + c4 * 4) =
                *(const float4*)(hidden + (size_t)r * 64 + c4 * 4);
            *(float4*)(g_h_new + (size_t)r * 64 + c4 * 4) = make_float4(0.f, 0.f, 0.f, 0.f);
        }
    }
    __syncthreads();

    int lane = t & 31, w = t >> 5;
    int mr = w * 16;
    int qr = lane >> 2, qc = (lane & 3) * 4;
    float acc[8][4];
#pragma unroll
    for (int n = 0; n < 8; n++)
#pragma unroll
        for (int q = 0; q < 4; q++) acc[n][q] = 0.f;

#pragma unroll
    for (int k0 = 0; k0 < 128; k0 += 16) {
        int c0 = k0 >> 3, c1 = c0 + 1;
        unsigned a0 = *(unsigned*)(As + swz(mr + qr, c0) + qc);
        unsigned a1 = *(unsigned*)(As + swz(mr + qr + 8, c0) + qc);
        unsigned a2 = *(unsigned*)(As + swz(mr + qr, c1) + qc);
        unsigned a3 = *(unsigned*)(As + swz(mr + qr + 8, c1) + qc);
#pragma unroll
        for (int nt = 0; nt < 8; nt++) {
            unsigned b0 = *(unsigned*)(Bs + swz(nt * 8 + qr, c0) + qc);
            unsigned b1 = *(unsigned*)(Bs + swz(nt * 8 + qr, c1) + qc);
            mma16816(acc[nt], a0, a1, a2, a3, b0, b1);
        }
    }
    __syncthreads();
#pragma unroll
    for (int nt = 0; nt < 8; nt++) {
        int col = nt * 8 + (lane & 3) * 2;
        *(float2*)(Ms + (mr + qr) * 68 + col)     = make_float2(acc[nt][0], acc[nt][1]);
        *(float2*)(Ms + (mr + qr + 8) * 68 + col) = make_float2(acc[nt][2], acc[nt][3]);
    }
    __syncthreads();
#pragma unroll
    for (int i = 0; i < 8; i++) {
        int idx = i * 256 + t;
        int row = idx >> 4, c4 = idx & 15;
        int r = base + row;
        if (r < N)
            *(float4*)(g_packed + (size_t)r * 128 + c4 * 4) = *(float4*)(Ms + row * 68 + c4 * 4);
    }
}

// ---------------- fused edge kernel ---------------------------------------
// Round-4 proven GEMM + phase2; additions: L1 prefetch of gather rows and
// __ldcs streaming loads for edge_feats (hint-only, numerics unchanged).
__global__ void edge_kernel(const float* __restrict__ ef,
                            const int* __restrict__ src,
                            const int* __restrict__ dst,
                            int E) {
    __shared__ __align__(16) char sm[49152];
    char* As = sm;                 // 128 x 256B bf16
    char* Bs = sm + 32768;         // 64 x 256B bf16
    float* Ms = (float*)sm;        // overlay [128][68] fp32
    int t = threadIdx.x;
    int lane = t & 31, w = t >> 5;
    int base = blockIdx.x * 128;
    int eclamp = E - 1;

    // ---- phase 0: L1-prefetch this warp's 16 gather rows (64 x 128B) ------
#pragma unroll
    for (int u = lane; u < 64; u += 32) {
        int ei = base + w * 16 + (u >> 2);
        if (ei > eclamp) ei = eclamp;
        int s = __ldg(src + ei);
        const char* gp = (const char*)(g_packed + (size_t)s * 128) + (u & 3) * 128;
        asm volatile("prefetch.global.L1 [%0];" :: "l"(gp));
    }

    // ---- phase 1: A tile load (streaming) + convert, B copy ---------------
#pragma unroll
    for (int i = 0; i < 16; i++) {
        int idx = i * 256 + t;
        int row = idx >> 5, col4 = idx & 31;
        int r = base + row; if (r >= E) r = E - 1;
        float4 v = __ldcs((const float4*)(ef + (size_t)r * 128 + col4 * 4));
        unsigned p0 = f2bf2(v.x, v.y), p1 = f2bf2(v.z, v.w);
        *(uint2*)(As + swz(row, col4 >> 1) + (col4 & 1) * 8) = make_uint2(p0, p1);
    }
#pragma unroll
    for (int i = 0; i < 4; i++) ((uint4*)Bs)[i * 256 + t] = g_Wb_edge[i * 256 + t];
    __syncthreads();

    // ---- GEMM (scalar fragment loads; proven) ------------------------------
    int mr = w * 16;
    int qr = lane >> 2, qc = (lane & 3) * 4;
    float acc[8][4];
#pragma unroll
    for (int n = 0; n < 8; n++)
#pragma unroll
        for (int q = 0; q < 4; q++) acc[n][q] = 0.f;

#pragma unroll
    for (int k0 = 0; k0 < 128; k0 += 16) {
        int c0 = k0 >> 3, c1 = c0 + 1;
        unsigned a0 = *(unsigned*)(As + swz(mr + qr, c0) + qc);
        unsigned a1 = *(unsigned*)(As + swz(mr + qr + 8, c0) + qc);
        unsigned a2 = *(unsigned*)(As + swz(mr + qr, c1) + qc);
        unsigned a3 = *(unsigned*)(As + swz(mr + qr + 8, c1) + qc);
#pragma unroll
        for (int nt = 0; nt < 8; nt++) {
            unsigned b0 = *(unsigned*)(Bs + swz(nt * 8 + qr, c0) + qc);
            unsigned b1 = *(unsigned*)(Bs + swz(nt * 8 + qr, c1) + qc);
            mma16816(acc[nt], a0, a1, a2, a3, b0, b1);
        }
    }
    __syncthreads();   // done reading As/Bs; overlay Ms
#pragma unroll
    for (int nt = 0; nt < 8; nt++) {
        int col = nt * 8 + (lane & 3) * 2;
        *(float2*)(Ms + (mr + qr) * 68 + col)     = make_float2(acc[nt][0], acc[nt][1]);
        *(float2*)(Ms + (mr + qr + 8) * 68 + col) = make_float2(acc[nt][2], acc[nt][3]);
    }
    __syncthreads();

    // ---- phase 2: 2 edges per warp iteration (gathers now hit L1) ---------
    int half = lane >> 4;          // 0 or 1
    int hl = lane & 15;            // 0..15
    if (base + 128 <= E) {
#pragma unroll 4
        for (int i = 0; i < 8; i++) {
            int ea = w * 16 + 2 * i;
            int gea = base + ea;
            int sa = __ldg(src + gea), sb = __ldg(src + gea + 1);
            int da = __ldg(dst + gea), db = __ldg(dst + gea + 1);
            float4 ga = __ldg((const float4*)(g_packed + (size_t)sa * 128) + lane);
            float4 gb = __ldg((const float4*)(g_packed + (size_t)sb * 128) + lane);
            float4 gbx;
            gbx.x = __shfl_xor_sync(0xffffffffu, gb.x, 16);
            gbx.y = __shfl_xor_sync(0xffffffffu, gb.y, 16);
            gbx.z = __shfl_xor_sync(0xffffffffu, gb.z, 16);
            gbx.w = __shfl_xor_sync(0xffffffffu, gb.w, 16);
            float4 proj = half ? gbx : ga;   // proj of MY edge, cols hl*4..
            float4 hidv = half ? ga : gbx;   // hidden of the OTHER edge
            float4 msg = *(float4*)(Ms + (size_t)(ea + half) * 68 + hl * 4);
            float v0 = proj.x + msg.x, v1 = proj.y + msg.y;
            float v2 = proj.z + msg.z, v3 = proj.w + msg.w;
            float mx = fmaxf(fmaxf(v0, v1), fmaxf(v2, v3));
#pragma unroll
            for (int o = 8; o > 0; o >>= 1)
                mx = fmaxf(mx, __shfl_xor_sync(0xffffffffu, mx, o));
            float e0 = __expf(v0 - mx), e1 = __expf(v1 - mx);
            float e2 = __expf(v2 - mx), e3 = __expf(v3 - mx);
            float ssum = (e0 + e1) + (e2 + e3);
#pragma unroll
            for (int o = 8; o > 0; o >>= 1)
                ssum += __shfl_xor_sync(0xffffffffu, ssum, o);
            float inv = 1.0f / ssum;
            float a0 = e0 * inv, a1 = e1 * inv, a2 = e2 * inv, a3 = e3 * inv;
            float b0 = __shfl_xor_sync(0xffffffffu, a0, 16);
            float b1 = __shfl_xor_sync(0xffffffffu, a1, 16);
            float b2 = __shfl_xor_sync(0xffffffffu, a2, 16);
            float b3 = __shfl_xor_sync(0xffffffffu, a3, 16);
            float m0 = hidv.x * b0, m1 = hidv.y * b1;
            float m2 = hidv.z * b2, m3 = hidv.w * b3;
            float* addr = g_h_new + (size_t)(half ? da : db) * 64 + hl * 4;
            asm volatile("red.global.add.v4.f32 [%0], {%1, %2, %3, %4};"
                         :: "l"(addr), "f"(m0), "f"(m1), "f"(m2), "f"(m3) : "memory");
        }
    } else {
        // tail tile: per-edge path (32 lanes x float2)
        for (int i = 0; i < 16; i++) {
            int e = w * 16 + i;
            int ge = base + e;
            if (ge >= E) break;
            int s = __ldg(src + ge);
            int d = __ldg(dst + ge);
            float2 mv  = *(float2*)(Ms + (size_t)e * 68 + lane * 2);
            float2 npv = *(const float2*)(g_packed + (size_t)s * 128 + lane * 2);
            float v0 = mv.x + npv.x;
            float v1 = mv.y + npv.y;
            float mx = fmaxf(v0, v1);
#pragma unroll
            for (int o = 16; o > 0; o >>= 1) mx = fmaxf(mx, __shfl_xor_sync(0xffffffffu, mx, o));
            float e0 = __expf(v0 - mx);
            float e1 = __expf(v1 - mx);
            float ssum = e0 + e1;
#pragma unroll
            for (int o = 16; o > 0; o >>= 1) ssum += __shfl_xor_sync(0xffffffffu, ssum, o);
            float inv = 1.0f / ssum;
            float2 hv = *(const float2*)(g_packed + (size_t)s * 128 + 64 + lane * 2);
            float o0 = hv.x * e0 * inv;
            float o1 = hv.y * e1 * inv;
            float* addr = g_h_new + (size_t)d * 64 + lane * 2;
            asm volatile("red.global.add.v2.f32 [%0], {%1, %2};"
                         :: "l"(addr), "f"(o0), "f"(o1) : "memory");
        }
    }
}

// ---------------- GRU kernel (bf16 mma, m32 x n64 warp tiles) -------------
// Retile: warp covers 32 rows x 64 cols -> per k-step LDS count 36 -> 24.
__global__ void gru_kernel(const float* __restrict__ hidden,
                           const float* __restrict__ b_ih,
                           const float* __restrict__ b_hh,
                           float* __restrict__ out, int N) {
    extern __shared__ __align__(16) char dsm[];
    char* As = dsm;                // 64 x 256B
    char* Bs = dsm + 16384;        // 256 x 256B
    float* Gs = (float*)dsm;       // overlay [64][260]
    int t = threadIdx.x;
    int base = blockIdx.x * 64;

#pragma unroll
    for (int i = 0; i < 8; i++) {
        int idx = i * 256 + t;
        int row = idx >> 5, col4 = idx & 31;
        int r = base + row; if (r >= N) r = N - 1;
        const float* p = (col4 < 16) ? (g_h_new + (size_t)r * 64 + col4 * 4)
                                     : (hidden  + (size_t)r * 64 + (col4 - 16) * 4);
        float4 v = *(const float4*)p;
        unsigned p0 = f2bf2(v.x, v.y), p1 = f2bf2(v.z, v.w);
        *(uint2*)(As + swz(row, col4 >> 1) + (col4 & 1) * 8) = make_uint2(p0, p1);
    }
#pragma unroll
    for (int i = 0; i < 16; i++) ((uint4*)Bs)[i * 256 + t] = g_Wb_big[i * 256 + t];
    __syncthreads();

    int lane = t & 31, w = t >> 5;
    int mr = (w & 1) * 32;             // 2 m-groups of 32 rows
    int ncb = (w >> 1) * 64;           // 4 n-groups of 64 cols
    int qr = lane >> 2, qc = (lane & 3) * 4;
    float acc[2][8][4];
#pragma unroll
    for (int mt = 0; mt < 2; mt++)
#pragma unroll
        for (int n = 0; n < 8; n++)
#pragma unroll
            for (int q = 0; q < 4; q++) acc[mt][n][q] = 0.f;

#pragma unroll
    for (int k0 = 0; k0 < 128; k0 += 16) {
        int c0 = k0 >> 3, c1 = c0 + 1;
        unsigned a[2][4];
#pragma unroll
        for (int mt = 0; mt < 2; mt++) {
            int rowm = mr + mt * 16;
            a[mt][0] = *(unsigned*)(As + swz(rowm + qr, c0) + qc);
            a[mt][1] = *(unsigned*)(As + swz(rowm + qr + 8, c0) + qc);
            a[mt][2] = *(unsigned*)(As + swz(rowm + qr, c1) + qc);
            a[mt][3] = *(unsigned*)(As + swz(rowm + qr + 8, c1) + qc);
        }
#pragma unroll
        for (int nt = 0; nt < 8; nt++) {
            int rb = ncb + nt * 8 + qr;
            unsigned b0 = *(unsigned*)(Bs + swz(rb, c0) + qc);
            unsigned b1 = *(unsigned*)(Bs + swz(rb, c1) + qc);
            mma16816(acc[0][nt], a[0][0], a[0][1], a[0][2], a[0][3], b0, b1);
            mma16816(acc[1][nt], a[1][0], a[1][1], a[1][2], a[1][3], b0, b1);
        }
    }
    __syncthreads();
#pragma unroll
    for (int mt = 0; mt < 2; mt++)
#pragma unroll
        for (int nt = 0; nt < 8; nt++) {
            int col = ncb + nt * 8 + (lane & 3) * 2;
            int rowm = mr + mt * 16;
            *(float2*)(Gs + (rowm + qr) * 260 + col)     = make_float2(acc[mt][nt][0], acc[mt][nt][1]);
            *(float2*)(Gs + (rowm + qr + 8) * 260 + col) = make_float2(acc[mt][nt][2], acc[mt][nt][3]);
        }
    __syncthreads();

    int row = t >> 2;                 // 0..63
    int jb = (t & 3) * 16;
    int gr_ = base + row;
    if (gr_ < N) {
#pragma unroll
        for (int jj = 0; jj < 16; jj++) {
            int j = jb + jj;
            float pr = Gs[row * 260 + j]       + b_ih[j]        + b_hh[j];
            float pz = Gs[row * 260 + 64 + j]  + b_ih[64 + j]   + b_hh[64 + j];
            float pi = Gs[row * 260 + 128 + j] + b_ih[128 + j];
            float ph = Gs[row * 260 + 192 + j] + b_hh[128 + j];
            float r = 1.0f / (1.0f + __expf(-pr));
            float z = 1.0f / (1.0f + __expf(-pz));
            float ng = tanhf(fmaf(r, ph, pi));
            float h = hidden[(size_t)gr_ * 64 + j];
            out[(size_t)gr_ * 64 + j] = fmaf(1.0f - z, ng, z * h);
        }
    }
}

// ---------------- launch --------------------------------------------------
extern "C" void kernel_launch(void* const* d_in, const int* in_sizes, int n_in,
                              void* d_out, int out_size) {
    const float* node_feats  = (const float*)d_in[0];
    const float* edge_feats  = (const float*)d_in[1];
    const float* node_hidden = (const float*)d_in[2];
    const int*   src         = (const int*)d_in[3];
    const int*   dst         = (const int*)d_in[4];
    const float* W_edge      = (const float*)d_in[5];
    const float* W_node      = (const float*)d_in[6];
    const float* W_ih        = (const float*)d_in[7];
    const float* W_hh        = (const float*)d_in[8];
    const float* b_ih        = (const float*)d_in[9];
    const float* b_hh        = (const float*)d_in[10];
    float* out = (float*)d_out;

    int E = in_sizes[3];
    int N = in_sizes[2] / HID;

    prep_kernel<<<24, 256>>>(W_edge, W_node, W_ih, W_hh);

    nodeproj_kernel<<<(N + 127) / 128, 256>>>(node_feats, node_hidden, N);

    edge_kernel<<<(E + 127) / 128, 256>>>(edge_feats, src, dst, E);

    static const int GRU_SMEM = 16384 + 65536;    // 80 KB dynamic
    cudaFuncSetAttribute(gru_kernel, cudaFuncAttributeMaxDynamicSharedMemorySize, GRU_SMEM);
    gru_kernel<<<(N + 63) / 64, 256, GRU_SMEM>>>(node_hidden, b_ih, b_hh, out, N);
}

// round 10
// speedup vs baseline: 1.2361x; 1.0769x over previous
#include <cuda_runtime.h>
#include <math.h>

#define HID 64
#define MAX_N 100000
#define MAX_E 1600000

// ---------------- device scratch (no allocations allowed) ----------------
// packed per-node gather row: [0:64)=node_proj, [64:128)=node_hidden (51.2MB)
__device__ float g_packed[MAX_N * 128];
__device__ float g_h_new[MAX_N * HID];       // 25.6 MB
// bf16 weight images, pre-swizzled into the smem tile layout:
// tile row stride 256B (128 bf16), 16B chunks, chunk c of row r stored at
// byte r*256 + ((c ^ (r&7))*16).
__device__ uint4 g_Wb_edge[64 * 16];         // W_edge  [j][k] bf16
__device__ uint4 g_Wb_node[64 * 16];         // W_node  [j][k] bf16
__device__ uint4 g_Wb_big[256 * 16];         // fused GRU weights [j][k] bf16

// ---------------- helpers -------------------------------------------------
__device__ __forceinline__ unsigned f2bf2(float lo, float hi) {
    unsigned r;
    asm("cvt.rn.bf16x2.f32 %0, %1, %2;" : "=r"(r) : "f"(hi), "f"(lo));
    return r;
}

__device__ __forceinline__ int swz(int row, int chunk) {
    return row * 256 + ((chunk ^ (row & 7)) << 4);
}

__device__ __forceinline__ void mma16816(float c[4],
                                         unsigned a0, unsigned a1,
                                         unsigned a2, unsigned a3,
                                         unsigned b0, unsigned b1) {
    asm("mma.sync.aligned.m16n8k16.row.col.f32.bf16.bf16.f32 "
        "{%0,%1,%2,%3},{%4,%5,%6,%7},{%8,%9},{%0,%1,%2,%3};"
        : "+f"(c[0]), "+f"(c[1]), "+f"(c[2]), "+f"(c[3])
        : "r"(a0), "r"(a1), "r"(a2), "r"(a3), "r"(b0), "r"(b1));
}

// ---------------- weight prep: bf16 convert + swizzle + GRU fusion --------
// Fused GRU weight [j][k], j in [0,256), k in [0,128):
//   cols of G: [0:64)=r pre-act, [64:128)=z, [128:192)=gi_n, [192:256)=gh_n
__global__ void prep_kernel(const float* __restrict__ W_edge,
                            const float* __restrict__ W_node,
                            const float* __restrict__ W_ih,
                            const float* __restrict__ W_hh) {
    int idx = blockIdx.x * blockDim.x + threadIdx.x;  // one 16B chunk each
    float v[8];
    uint4* dst;
    if (idx < 1024) {
        int j = idx >> 4, c = idx & 15;
        const float* p = W_edge + j * 128 + c * 8;
#pragma unroll
        for (int i = 0; i < 8; i++) v[i] = p[i];
        dst = g_Wb_edge + (j * 16 + (c ^ (j & 7)));
    } else if (idx < 2048) {
        int i2 = idx - 1024;
        int j = i2 >> 4, c = i2 & 15;
        const float* p = W_node + j * 128 + c * 8;
#pragma unroll
        for (int i = 0; i < 8; i++) v[i] = p[i];
        dst = g_Wb_node + (j * 16 + (c ^ (j & 7)));
    } else if (idx < 6144) {
        int i3 = idx - 2048;
        int j = i3 >> 4, c = i3 & 15;
#pragma unroll
        for (int i = 0; i < 8; i++) {
            int k = c * 8 + i;
            float val = 0.f;
            if (k < 64) {
                if (j < 192) val = W_ih[j * 64 + k];
            } else {
                int kk = k - 64;
                if (j < 128)       val = W_hh[j * 64 + kk];
                else if (j >= 192) val = W_hh[(j - 64) * 64 + kk];
            }
            v[i] = val;
        }
        dst = g_Wb_big + (j * 16 + (c ^ (j & 7)));
    } else {
        return;
    }
    uint4 o;
    o.x = f2bf2(v[0], v[1]);
    o.y = f2bf2(v[2], v[3]);
    o.z = f2bf2(v[4], v[5]);
    o.w = f2bf2(v[6], v[7]);
    *dst = o;
}

// ---------------- node_proj + pack hidden + zero h_new --------------------
__global__ void nodeproj_kernel(const float* __restrict__ nf,
                                const float* __restrict__ hidden, int N) {
    __shared__ __align__(16) char sm[49152];
    char* As = sm;                 // 128 x 256B bf16, swizzled
    char* Bs = sm + 32768;         // 64 x 256B bf16, swizzled
    float* Ms = (float*)sm;        // overlay [128][68] fp32 staging
    int t = threadIdx.x;
    int base = blockIdx.x * 128;

#pragma unroll
    for (int i = 0; i < 16; i++) {
        int idx = i * 256 + t;
        int row = idx >> 5, col4 = idx & 31;
        int r = base + row; if (r >= N) r = N - 1;
        float4 v = *(const float4*)(nf + (size_t)r * 128 + col4 * 4);
        unsigned p0 = f2bf2(v.x, v.y), p1 = f2bf2(v.z, v.w);
        *(uint2*)(As + swz(row, col4 >> 1) + (col4 & 1) * 8) = make_uint2(p0, p1);
    }
#pragma unroll
    for (int i = 0; i < 4; i++) ((uint4*)Bs)[i * 256 + t] = g_Wb_node[i * 256 + t];

    // hidden copy + h_new zero for this block's rows (independent of GEMM)
#pragma unroll
    for (int i = 0; i < 8; i++) {
        int idx = i * 256 + t;           // 2048 float4 chunks
        int row = idx >> 4, c4 = idx & 15;
        int r = base + row;
        if (r < N) {
            *(float4*)(g_packed + (size_t)r * 128 + 64 + c4 * 4) =
                *(const float4*)(hidden + (size_t)r * 64 + c4 * 4);
            *(float4*)(g_h_new + (size_t)r * 64 + c4 * 4) = make_float4(0.f, 0.f, 0.f, 0.f);
        }
    }
    __syncthreads();

    int lane = t & 31, w = t >> 5;
    int mr = w * 16;
    int qr = lane >> 2, qc = (lane & 3) * 4;
    float acc[8][4];
#pragma unroll
    for (int n = 0; n < 8; n++)
#pragma unroll
        for (int q = 0; q < 4; q++) acc[n][q] = 0.f;

#pragma unroll
    for (int k0 = 0; k0 < 128; k0 += 16) {
        int c0 = k0 >> 3, c1 = c0 + 1;
        unsigned a0 = *(unsigned*)(As + swz(mr + qr, c0) + qc);
        unsigned a1 = *(unsigned*)(As + swz(mr + qr + 8, c0) + qc);
        unsigned a2 = *(unsigned*)(As + swz(mr + qr, c1) + qc);
        unsigned a3 = *(unsigned*)(As + swz(mr + qr + 8, c1) + qc);
#pragma unroll
        for (int nt = 0; nt < 8; nt++) {
            unsigned b0 = *(unsigned*)(Bs + swz(nt * 8 + qr, c0) + qc);
            unsigned b1 = *(unsigned*)(Bs + swz(nt * 8 + qr, c1) + qc);
            mma16816(acc[nt], a0, a1, a2, a3, b0, b1);
        }
    }
    __syncthreads();
#pragma unroll
    for (int nt = 0; nt < 8; nt++) {
        int col = nt * 8 + (lane & 3) * 2;
        *(float2*)(Ms + (mr + qr) * 68 + col)     = make_float2(acc[nt][0], acc[nt][1]);
        *(float2*)(Ms + (mr + qr + 8) * 68 + col) = make_float2(acc[nt][2], acc[nt][3]);
    }
    __syncthreads();
#pragma unroll
    for (int i = 0; i < 8; i++) {
        int idx = i * 256 + t;
        int row = idx >> 4, c4 = idx & 15;
        int r = base + row;
        if (r < N)
            *(float4*)(g_packed + (size_t)r * 128 + c4 * 4) = *(float4*)(Ms + row * 68 + c4 * 4);
    }
}

// ---------------- fused edge kernel ---------------------------------------
// Round-4 proven GEMM + phase2 + L1 prefetch + __ldcs; launch_bounds forces
// 64 regs -> 4 blocks/SM (was 3) for latency hiding.
__global__ void __launch_bounds__(256, 4)
edge_kernel(const float* __restrict__ ef,
            const int* __restrict__ src,
            const int* __restrict__ dst,
            int E) {
    __shared__ __align__(16) char sm[49152];
    char* As = sm;                 // 128 x 256B bf16
    char* Bs = sm + 32768;         // 64 x 256B bf16
    float* Ms = (float*)sm;        // overlay [128][68] fp32
    int t = threadIdx.x;
    int lane = t & 31, w = t >> 5;
    int base = blockIdx.x * 128;
    int eclamp = E - 1;

    // ---- phase 0: L1-prefetch this warp's 16 gather rows (64 x 128B) ------
#pragma unroll
    for (int u = lane; u < 64; u += 32) {
        int ei = base + w * 16 + (u >> 2);
        if (ei > eclamp) ei = eclamp;
        int s = __ldg(src + ei);
        const char* gp = (const char*)(g_packed + (size_t)s * 128) + (u & 3) * 128;
        asm volatile("prefetch.global.L1 [%0];" :: "l"(gp));
    }

    // ---- phase 1: A tile load (streaming) + convert, B copy ---------------
#pragma unroll
    for (int i = 0; i < 16; i++) {
        int idx = i * 256 + t;
        int row = idx >> 5, col4 = idx & 31;
        int r = base + row; if (r >= E) r = E - 1;
        float4 v = __ldcs((const float4*)(ef + (size_t)r * 128 + col4 * 4));
        unsigned p0 = f2bf2(v.x, v.y), p1 = f2bf2(v.z, v.w);
        *(uint2*)(As + swz(row, col4 >> 1) + (col4 & 1) * 8) = make_uint2(p0, p1);
    }
#pragma unroll
    for (int i = 0; i < 4; i++) ((uint4*)Bs)[i * 256 + t] = g_Wb_edge[i * 256 + t];
    __syncthreads();

    // ---- GEMM (scalar fragment loads; proven) ------------------------------
    int mr = w * 16;
    int qr = lane >> 2, qc = (lane & 3) * 4;
    float acc[8][4];
#pragma unroll
    for (int n = 0; n < 8; n++)
#pragma unroll
        for (int q = 0; q < 4; q++) acc[n][q] = 0.f;

#pragma unroll
    for (int k0 = 0; k0 < 128; k0 += 16) {
        int c0 = k0 >> 3, c1 = c0 + 1;
        unsigned a0 = *(unsigned*)(As + swz(mr + qr, c0) + qc);
        unsigned a1 = *(unsigned*)(As + swz(mr + qr + 8, c0) + qc);
        unsigned a2 = *(unsigned*)(As + swz(mr + qr, c1) + qc);
        unsigned a3 = *(unsigned*)(As + swz(mr + qr + 8, c1) + qc);
#pragma unroll
        for (int nt = 0; nt < 8; nt++) {
            unsigned b0 = *(unsigned*)(Bs + swz(nt * 8 + qr, c0) + qc);
            unsigned b1 = *(unsigned*)(Bs + swz(nt * 8 + qr, c1) + qc);
            mma16816(acc[nt], a0, a1, a2, a3, b0, b1);
        }
    }
    __syncthreads();   // done reading As/Bs; overlay Ms
#pragma unroll
    for (int nt = 0; nt < 8; nt++) {
        int col = nt * 8 + (lane & 3) * 2;
        *(float2*)(Ms + (mr + qr) * 68 + col)     = make_float2(acc[nt][0], acc[nt][1]);
        *(float2*)(Ms + (mr + qr + 8) * 68 + col) = make_float2(acc[nt][2], acc[nt][3]);
    }
    __syncthreads();

    // ---- phase 2: 2 edges per warp iteration (gathers hit L1) -------------
    int half = lane >> 4;          // 0 or 1
    int hl = lane & 15;            // 0..15
    if (base + 128 <= E) {
#pragma unroll 4
        for (int i = 0; i < 8; i++) {
            int ea = w * 16 + 2 * i;
            int gea = base + ea;
            int sa = __ldg(src + gea), sb = __ldg(src + gea + 1);
            int da = __ldg(dst + gea), db = __ldg(dst + gea + 1);
            float4 ga = __ldg((const float4*)(g_packed + (size_t)sa * 128) + lane);
            float4 gb = __ldg((const float4*)(g_packed + (size_t)sb * 128) + lane);
            float4 gbx;
            gbx.x = __shfl_xor_sync(0xffffffffu, gb.x, 16);
            gbx.y = __shfl_xor_sync(0xffffffffu, gb.y, 16);
            gbx.z = __shfl_xor_sync(0xffffffffu, gb.z, 16);
            gbx.w = __shfl_xor_sync(0xffffffffu, gb.w, 16);
            float4 proj = half ? gbx : ga;   // proj of MY edge, cols hl*4..
            float4 hidv = half ? ga : gbx;   // hidden of the OTHER edge
            float4 msg = *(float4*)(Ms + (size_t)(ea + half) * 68 + hl * 4);
            float v0 = proj.x + msg.x, v1 = proj.y + msg.y;
            float v2 = proj.z + msg.z, v3 = proj.w + msg.w;
            float mx = fmaxf(fmaxf(v0, v1), fmaxf(v2, v3));
#pragma unroll
            for (int o = 8; o > 0; o >>= 1)
                mx = fmaxf(mx, __shfl_xor_sync(0xffffffffu, mx, o));
            float e0 = __expf(v0 - mx), e1 = __expf(v1 - mx);
            float e2 = __expf(v2 - mx), e3 = __expf(v3 - mx);
            float ssum = (e0 + e1) + (e2 + e3);
#pragma unroll
            for (int o = 8; o > 0; o >>= 1)
                ssum += __shfl_xor_sync(0xffffffffu, ssum, o);
            float inv = 1.0f / ssum;
            float a0 = e0 * inv, a1 = e1 * inv, a2 = e2 * inv, a3 = e3 * inv;
            float b0 = __shfl_xor_sync(0xffffffffu, a0, 16);
            float b1 = __shfl_xor_sync(0xffffffffu, a1, 16);
            float b2 = __shfl_xor_sync(0xffffffffu, a2, 16);
            float b3 = __shfl_xor_sync(0xffffffffu, a3, 16);
            float m0 = hidv.x * b0, m1 = hidv.y * b1;
            float m2 = hidv.z * b2, m3 = hidv.w * b3;
            float* addr = g_h_new + (size_t)(half ? da : db) * 64 + hl * 4;
            asm volatile("red.global.add.v4.f32 [%0], {%1, %2, %3, %4};"
                         :: "l"(addr), "f"(m0), "f"(m1), "f"(m2), "f"(m3) : "memory");
        }
    } else {
        // tail tile: per-edge path (32 lanes x float2)
        for (int i = 0; i < 16; i++) {
            int e = w * 16 + i;
            int ge = base + e;
            if (ge >= E) break;
            int s = __ldg(src + ge);
            int d = __ldg(dst + ge);
            float2 mv  = *(float2*)(Ms + (size_t)e * 68 + lane * 2);
            float2 npv = *(const float2*)(g_packed + (size_t)s * 128 + lane * 2);
            float v0 = mv.x + npv.x;
            float v1 = mv.y + npv.y;
            float mx = fmaxf(v0, v1);
#pragma unroll
            for (int o = 16; o > 0; o >>= 1) mx = fmaxf(mx, __shfl_xor_sync(0xffffffffu, mx, o));
            float e0 = __expf(v0 - mx);
            float e1 = __expf(v1 - mx);
            float ssum = e0 + e1;
#pragma unroll
            for (int o = 16; o > 0; o >>= 1) ssum += __shfl_xor_sync(0xffffffffu, ssum, o);
            float inv = 1.0f / ssum;
            float2 hv = *(const float2*)(g_packed + (size_t)s * 128 + 64 + lane * 2);
            float o0 = hv.x * e0 * inv;
            float o1 = hv.y * e1 * inv;
            float* addr = g_h_new + (size_t)d * 64 + lane * 2;
            asm volatile("red.global.add.v2.f32 [%0], {%1, %2};"
                         :: "l"(addr), "f"(o0), "f"(o1) : "memory");
        }
    }
}

// ---------------- GRU kernel (round-4 version: m16 x n128 warp tiles) -----
__global__ void gru_kernel(const float* __restrict__ hidden,
                           const float* __restrict__ b_ih,
                           const float* __restrict__ b_hh,
                           float* __restrict__ out, int N) {
    extern __shared__ __align__(16) char dsm[];
    char* As = dsm;                // 64 x 256B
    char* Bs = dsm + 16384;        // 256 x 256B
    float* Gs = (float*)dsm;       // overlay [64][260]
    int t = threadIdx.x;
    int base = blockIdx.x * 64;

#pragma unroll
    for (int i = 0; i < 8; i++) {
        int idx = i * 256 + t;
        int row = idx >> 5, col4 = idx & 31;
        int r = base + row; if (r >= N) r = N - 1;
        const float* p = (col4 < 16) ? (g_h_new + (size_t)r * 64 + col4 * 4)
                                     : (hidden  + (size_t)r * 64 + (col4 - 16) * 4);
        float4 v = *(const float4*)p;
        unsigned p0 = f2bf2(v.x, v.y), p1 = f2bf2(v.z, v.w);
        *(uint2*)(As + swz(row, col4 >> 1) + (col4 & 1) * 8) = make_uint2(p0, p1);
    }
#pragma unroll
    for (int i = 0; i < 16; i++) ((uint4*)Bs)[i * 256 + t] = g_Wb_big[i * 256 + t];
    __syncthreads();

    int lane = t & 31, w = t >> 5;
    int mr = (w & 3) * 16;
    int ncb = (w >> 2) * 128;
    int qr = lane >> 2, qc = (lane & 3) * 4;
    float acc[16][4];
#pragma unroll
    for (int n = 0; n < 16; n++)
#pragma unroll
        for (int q = 0; q < 4; q++) acc[n][q] = 0.f;

#pragma unroll
    for (int k0 = 0; k0 < 128; k0 += 16) {
        int c0 = k0 >> 3, c1 = c0 + 1;
        unsigned a0 = *(unsigned*)(As + swz(mr + qr, c0) + qc);
        unsigned a1 = *(unsigned*)(As + swz(mr + qr + 8, c0) + qc);
        unsigned a2 = *(unsigned*)(As + swz(mr + qr, c1) + qc);
        unsigned a3 = *(unsigned*)(As + swz(mr + qr + 8, c1) + qc);
#pragma unroll
        for (int nt = 0; nt < 16; nt++) {
            unsigned b0 = *(unsigned*)(Bs + swz(ncb + nt * 8 + qr, c0) + qc);
            unsigned b1 = *(unsigned*)(Bs + swz(ncb + nt * 8 + qr, c1) + qc);
            mma16816(acc[nt], a0, a1, a2, a3, b0, b1);
        }
    }
    __syncthreads();
#pragma unroll
    for (int nt = 0; nt < 16; nt++) {
        int col = ncb + nt * 8 + (lane & 3) * 2;
        *(float2*)(Gs + (mr + qr) * 260 + col)     = make_float2(acc[nt][0], acc[nt][1]);
        *(float2*)(Gs + (mr + qr + 8) * 260 + col) = make_float2(acc[nt][2], acc[nt][3]);
    }
    __syncthreads();

    int row = t >> 2;                 // 0..63
    int jb = (t & 3) * 16;
    int gr_ = base + row;
    if (gr_ < N) {
#pragma unroll
        for (int jj = 0; jj < 16; jj++) {
            int j = jb + jj;
            float pr = Gs[row * 260 + j]       + b_ih[j]        + b_hh[j];
            float pz = Gs[row * 260 + 64 + j]  + b_ih[64 + j]   + b_hh[64 + j];
            float pi = Gs[row * 260 + 128 + j] + b_ih[128 + j];
            float ph = Gs[row * 260 + 192 + j] + b_hh[128 + j];
            float r = 1.0f / (1.0f + __expf(-pr));
            float z = 1.0f / (1.0f + __expf(-pz));
            float ng = tanhf(fmaf(r, ph, pi));
            float h = hidden[(size_t)gr_ * 64 + j];
            out[(size_t)gr_ * 64 + j] = fmaf(1.0f - z, ng, z * h);
        }
    }
}

// ---------------- launch --------------------------------------------------
extern "C" void kernel_launch(void* const* d_in, const int* in_sizes, int n_in,
                              void* d_out, int out_size) {
    const float* node_feats  = (const float*)d_in[0];
    const float* edge_feats  = (const float*)d_in[1];
    const float* node_hidden = (const float*)d_in[2];
    const int*   src         = (const int*)d_in[3];
    const int*   dst         = (const int*)d_in[4];
    const float* W_edge      = (const float*)d_in[5];
    const float* W_node      = (const float*)d_in[6];
    const float* W_ih        = (const float*)d_in[7];
    const float* W_hh        = (const float*)d_in[8];
    const float* b_ih        = (const float*)d_in[9];
    const float* b_hh        = (const float*)d_in[10];
    float* out = (float*)d_out;

    int E = in_sizes[3];
    int N = in_sizes[2] / HID;

    prep_kernel<<<24, 256>>>(W_edge, W_node, W_ih, W_hh);

    nodeproj_kernel<<<(N + 127) / 128, 256>>>(node_feats, node_hidden, N);

    edge_kernel<<<(E + 127) / 128, 256>>>(edge_feats, src, dst, E);

    static const int GRU_SMEM = 16384 + 65536;    // 80 KB dynamic
    cudaFuncSetAttribute(gru_kernel, cudaFuncAttributeMaxDynamicSharedMemorySize, GRU_SMEM);
    gru_kernel<<<(N + 63) / 64, 256, GRU_SMEM>>>(node_hidden, b_ih, b_hh, out, N);
}

// round 11
// speedup vs baseline: 1.2826x; 1.0376x over previous
#include <cuda_runtime.h>
#include <math.h>

#define HID 64
#define MAX_N 100000
#define MAX_E 1600000

// ---------------- device scratch (no allocations allowed) ----------------
// packed per-node gather row: [0:64)=node_proj, [64:128)=node_hidden (51.2MB)
__device__ float g_packed[MAX_N * 128];
__device__ float g_h_new[MAX_N * HID];       // 25.6 MB
// bf16 weight images, pre-swizzled into the smem tile layout:
// tile row stride 256B (128 bf16), 16B chunks, chunk c of row r stored at
// byte r*256 + ((c ^ (r&7))*16).
__device__ uint4 g_Wb_edge[64 * 16];         // W_edge  [j][k] bf16
__device__ uint4 g_Wb_node[64 * 16];         // W_node  [j][k] bf16
__device__ uint4 g_Wb_big[256 * 16];         // fused+interleaved GRU weights

// ---------------- helpers -------------------------------------------------
__device__ __forceinline__ unsigned f2bf2(float lo, float hi) {
    unsigned r;
    asm("cvt.rn.bf16x2.f32 %0, %1, %2;" : "=r"(r) : "f"(hi), "f"(lo));
    return r;
}

__device__ __forceinline__ int swz(int row, int chunk) {
    return row * 256 + ((chunk ^ (row & 7)) << 4);
}

__device__ __forceinline__ void mma16816(float c[4],
                                         unsigned a0, unsigned a1,
                                         unsigned a2, unsigned a3,
                                         unsigned b0, unsigned b1) {
    asm("mma.sync.aligned.m16n8k16.row.col.f32.bf16.bf16.f32 "
        "{%0,%1,%2,%3},{%4,%5,%6,%7},{%8,%9},{%0,%1,%2,%3};"
        : "+f"(c[0]), "+f"(c[1]), "+f"(c[2]), "+f"(c[3])
        : "r"(a0), "r"(a1), "r"(a2), "r"(a3), "r"(b0), "r"(b1));
}

// ---------------- weight prep: bf16 convert + swizzle + GRU fusion --------
// g_Wb_big column positions are INTERLEAVED so each thread's MMA accumulators
// hold all 4 gates of one hidden dim:
//   p (0..255): half=p>>7, rem=p&127, nt=rem>>3, m=nt>>1, odd=nt&1,
//               qq=(rem>>1)&3, par=rem&1; j = half*32 + m*4 + qq;
//   original col o = (odd? (par?192:128) : (par?64:0)) + j
// Original fused cols: [0:64)=r pre-act, [64:128)=z, [128:192)=gi_n, [192:256)=gh_n
__global__ void prep_kernel(const float* __restrict__ W_edge,
                            const float* __restrict__ W_node,
                            const float* __restrict__ W_ih,
                            const float* __restrict__ W_hh) {
    int idx = blockIdx.x * blockDim.x + threadIdx.x;  // one 16B chunk each
    float v[8];
    uint4* dst;
    if (idx < 1024) {
        int j = idx >> 4, c = idx & 15;
        const float* p = W_edge + j * 128 + c * 8;
#pragma unroll
        for (int i = 0; i < 8; i++) v[i] = p[i];
        dst = g_Wb_edge + (j * 16 + (c ^ (j & 7)));
    } else if (idx < 2048) {
        int i2 = idx - 1024;
        int j = i2 >> 4, c = i2 & 15;
        const float* p = W_node + j * 128 + c * 8;
#pragma unroll
        for (int i = 0; i < 8; i++) v[i] = p[i];
        dst = g_Wb_node + (j * 16 + (c ^ (j & 7)));
    } else if (idx < 6144) {
        int i3 = idx - 2048;
        int p = i3 >> 4, c = i3 & 15;
        // decode interleaved position p -> original fused column o
        int half = p >> 7, rem = p & 127;
        int nt = rem >> 3, m = nt >> 1, odd = nt & 1;
        int qq = (rem >> 1) & 3, par = rem & 1;
        int j = half * 32 + m * 4 + qq;
        int o = (odd ? (par ? 192 : 128) : (par ? 64 : 0)) + j;
#pragma unroll
        for (int i = 0; i < 8; i++) {
            int k = c * 8 + i;
            float val = 0.f;
            if (k < 64) {
                if (o < 192) val = W_ih[o * 64 + k];
            } else {
                int kk = k - 64;
                if (o < 128)       val = W_hh[o * 64 + kk];
                else if (o >= 192) val = W_hh[(o - 64) * 64 + kk];
            }
            v[i] = val;
        }
        dst = g_Wb_big + (p * 16 + (c ^ (p & 7)));
    } else {
        return;
    }
    uint4 o4;
    o4.x = f2bf2(v[0], v[1]);
    o4.y = f2bf2(v[2], v[3]);
    o4.z = f2bf2(v[4], v[5]);
    o4.w = f2bf2(v[6], v[7]);
    *dst = o4;
}

// ---------------- node_proj + pack hidden + zero h_new --------------------
__global__ void nodeproj_kernel(const float* __restrict__ nf,
                                const float* __restrict__ hidden, int N) {
    __shared__ __align__(16) char sm[49152];
    char* As = sm;                 // 128 x 256B bf16, swizzled
    char* Bs = sm + 32768;         // 64 x 256B bf16, swizzled
    float* Ms = (float*)sm;        // overlay [128][68] fp32 staging
    int t = threadIdx.x;
    int base = blockIdx.x * 128;

    // A load: one 16B bf16 chunk (8 floats = 2 float4) per iter -> STS.128
#pragma unroll
    for (int i = 0; i < 8; i++) {
        int idx = i * 256 + t;
        int row = idx >> 4, c8 = idx & 15;
        int r = base + row; if (r >= N) r = N - 1;
        const float4* p = (const float4*)(nf + (size_t)r * 128 + c8 * 8);
        float4 v1 = p[0], v2 = p[1];
        uint4 o;
        o.x = f2bf2(v1.x, v1.y); o.y = f2bf2(v1.z, v1.w);
        o.z = f2bf2(v2.x, v2.y); o.w = f2bf2(v2.z, v2.w);
        *(uint4*)(As + swz(row, c8)) = o;
    }
#pragma unroll
    for (int i = 0; i < 4; i++) ((uint4*)Bs)[i * 256 + t] = g_Wb_node[i * 256 + t];

    // hidden copy + h_new zero for this block's rows (independent of GEMM)
#pragma unroll
    for (int i = 0; i < 8; i++) {
        int idx = i * 256 + t;           // 2048 float4 chunks
        int row = idx >> 4, c4 = idx & 15;
        int r = base + row;
        if (r < N) {
            *(float4*)(g_packed + (size_t)r * 128 + 64 + c4 * 4) =
                *(const float4*)(hidden + (size_t)r * 64 + c4 * 4);
            *(float4*)(g_h_new + (size_t)r * 64 + c4 * 4) = make_float4(0.f, 0.f, 0.f, 0.f);
        }
    }
    __syncthreads();

    int lane = t & 31, w = t >> 5;
    int mr = w * 16;
    int qr = lane >> 2, qc = (lane & 3) * 4;
    float acc[8][4];
#pragma unroll
    for (int n = 0; n < 8; n++)
#pragma unroll
        for (int q = 0; q < 4; q++) acc[n][q] = 0.f;

#pragma unroll
    for (int k0 = 0; k0 < 128; k0 += 16) {
        int c0 = k0 >> 3, c1 = c0 + 1;
        unsigned a0 = *(unsigned*)(As + swz(mr + qr, c0) + qc);
        unsigned a1 = *(unsigned*)(As + swz(mr + qr + 8, c0) + qc);
        unsigned a2 = *(unsigned*)(As + swz(mr + qr, c1) + qc);
        unsigned a3 = *(unsigned*)(As + swz(mr + qr + 8, c1) + qc);
#pragma unroll
        for (int nt = 0; nt < 8; nt++) {
            unsigned b0 = *(unsigned*)(Bs + swz(nt * 8 + qr, c0) + qc);
            unsigned b1 = *(unsigned*)(Bs + swz(nt * 8 + qr, c1) + qc);
            mma16816(acc[nt], a0, a1, a2, a3, b0, b1);
        }
    }
    __syncthreads();
#pragma unroll
    for (int nt = 0; nt < 8; nt++) {
        int col = nt * 8 + (lane & 3) * 2;
        *(float2*)(Ms + (mr + qr) * 68 + col)     = make_float2(acc[nt][0], acc[nt][1]);
        *(float2*)(Ms + (mr + qr + 8) * 68 + col) = make_float2(acc[nt][2], acc[nt][3]);
    }
    __syncthreads();
#pragma unroll
    for (int i = 0; i < 8; i++) {
        int idx = i * 256 + t;
        int row = idx >> 4, c4 = idx & 15;
        int r = base + row;
        if (r < N)
            *(float4*)(g_packed + (size_t)r * 128 + c4 * 4) = *(float4*)(Ms + row * 68 + c4 * 4);
    }
}

// ---------------- fused edge kernel ---------------------------------------
// Proven GEMM + phase2 + L1 prefetch + __ldcs; STS.128-packed A convert.
__global__ void __launch_bounds__(256, 4)
edge_kernel(const float* __restrict__ ef,
            const int* __restrict__ src,
            const int* __restrict__ dst,
            int E) {
    __shared__ __align__(16) char sm[49152];
    char* As = sm;                 // 128 x 256B bf16
    char* Bs = sm + 32768;         // 64 x 256B bf16
    float* Ms = (float*)sm;        // overlay [128][68] fp32
    int t = threadIdx.x;
    int lane = t & 31, w = t >> 5;
    int base = blockIdx.x * 128;
    int eclamp = E - 1;

    // ---- phase 0: L1-prefetch this warp's 16 gather rows (64 x 128B) ------
#pragma unroll
    for (int u = lane; u < 64; u += 32) {
        int ei = base + w * 16 + (u >> 2);
        if (ei > eclamp) ei = eclamp;
        int s = __ldg(src + ei);
        const char* gp = (const char*)(g_packed + (size_t)s * 128) + (u & 3) * 128;
        asm volatile("prefetch.global.L1 [%0];" :: "l"(gp));
    }

    // ---- phase 1: A tile load (streaming, STS.128 packed) + B copy --------
#pragma unroll
    for (int i = 0; i < 8; i++) {
        int idx = i * 256 + t;
        int row = idx >> 4, c8 = idx & 15;
        int r = base + row; if (r >= E) r = E - 1;
        const float4* p = (const float4*)(ef + (size_t)r * 128 + c8 * 8);
        float4 v1 = __ldcs(p), v2 = __ldcs(p + 1);
        uint4 o;
        o.x = f2bf2(v1.x, v1.y); o.y = f2bf2(v1.z, v1.w);
        o.z = f2bf2(v2.x, v2.y); o.w = f2bf2(v2.z, v2.w);
        *(uint4*)(As + swz(row, c8)) = o;
    }
#pragma unroll
    for (int i = 0; i < 4; i++) ((uint4*)Bs)[i * 256 + t] = g_Wb_edge[i * 256 + t];
    __syncthreads();

    // ---- GEMM (scalar fragment loads; proven) ------------------------------
    int mr = w * 16;
    int qr = lane >> 2, qc = (lane & 3) * 4;
    float acc[8][4];
#pragma unroll
    for (int n = 0; n < 8; n++)
#pragma unroll
        for (int q = 0; q < 4; q++) acc[n][q] = 0.f;

#pragma unroll
    for (int k0 = 0; k0 < 128; k0 += 16) {
        int c0 = k0 >> 3, c1 = c0 + 1;
        unsigned a0 = *(unsigned*)(As + swz(mr + qr, c0) + qc);
        unsigned a1 = *(unsigned*)(As + swz(mr + qr + 8, c0) + qc);
        unsigned a2 = *(unsigned*)(As + swz(mr + qr, c1) + qc);
        unsigned a3 = *(unsigned*)(As + swz(mr + qr + 8, c1) + qc);
#pragma unroll
        for (int nt = 0; nt < 8; nt++) {
            unsigned b0 = *(unsigned*)(Bs + swz(nt * 8 + qr, c0) + qc);
            unsigned b1 = *(unsigned*)(Bs + swz(nt * 8 + qr, c1) + qc);
            mma16816(acc[nt], a0, a1, a2, a3, b0, b1);
        }
    }
    __syncthreads();   // done reading As/Bs; overlay Ms
#pragma unroll
    for (int nt = 0; nt < 8; nt++) {
        int col = nt * 8 + (lane & 3) * 2;
        *(float2*)(Ms + (mr + qr) * 68 + col)     = make_float2(acc[nt][0], acc[nt][1]);
        *(float2*)(Ms + (mr + qr + 8) * 68 + col) = make_float2(acc[nt][2], acc[nt][3]);
    }
    __syncthreads();

    // ---- phase 2: 2 edges per warp iteration (gathers hit L1) -------------
    int half = lane >> 4;          // 0 or 1
    int hl = lane & 15;            // 0..15
    if (base + 128 <= E) {
#pragma unroll 4
        for (int i = 0; i < 8; i++) {
            int ea = w * 16 + 2 * i;
            int gea = base + ea;
            int sa = __ldg(src + gea), sb = __ldg(src + gea + 1);
            int da = __ldg(dst + gea), db = __ldg(dst + gea + 1);
            float4 ga = __ldg((const float4*)(g_packed + (size_t)sa * 128) + lane);
            float4 gb = __ldg((const float4*)(g_packed + (size_t)sb * 128) + lane);
            float4 gbx;
            gbx.x = __shfl_xor_sync(0xffffffffu, gb.x, 16);
            gbx.y = __shfl_xor_sync(0xffffffffu, gb.y, 16);
            gbx.z = __shfl_xor_sync(0xffffffffu, gb.z, 16);
            gbx.w = __shfl_xor_sync(0xffffffffu, gb.w, 16);
            float4 proj = half ? gbx : ga;   // proj of MY edge, cols hl*4..
            float4 hidv = half ? ga : gbx;   // hidden of the OTHER edge
            float4 msg = *(float4*)(Ms + (size_t)(ea + half) * 68 + hl * 4);
            float v0 = proj.x + msg.x, v1 = proj.y + msg.y;
            float v2 = proj.z + msg.z, v3 = proj.w + msg.w;
            float mx = fmaxf(fmaxf(v0, v1), fmaxf(v2, v3));
#pragma unroll
            for (int o = 8; o > 0; o >>= 1)
                mx = fmaxf(mx, __shfl_xor_sync(0xffffffffu, mx, o));
            float e0 = __expf(v0 - mx), e1 = __expf(v1 - mx);
            float e2 = __expf(v2 - mx), e3 = __expf(v3 - mx);
            float ssum = (e0 + e1) + (e2 + e3);
#pragma unroll
            for (int o = 8; o > 0; o >>= 1)
                ssum += __shfl_xor_sync(0xffffffffu, ssum, o);
            float inv = 1.0f / ssum;
            float a0 = e0 * inv, a1 = e1 * inv, a2 = e2 * inv, a3 = e3 * inv;
            float b0 = __shfl_xor_sync(0xffffffffu, a0, 16);
            float b1 = __shfl_xor_sync(0xffffffffu, a1, 16);
            float b2 = __shfl_xor_sync(0xffffffffu, a2, 16);
            float b3 = __shfl_xor_sync(0xffffffffu, a3, 16);
            float m0 = hidv.x * b0, m1 = hidv.y * b1;
            float m2 = hidv.z * b2, m3 = hidv.w * b3;
            float* addr = g_h_new + (size_t)(half ? da : db) * 64 + hl * 4;
            asm volatile("red.global.add.v4.f32 [%0], {%1, %2, %3, %4};"
                         :: "l"(addr), "f"(m0), "f"(m1), "f"(m2), "f"(m3) : "memory");
        }
    } else {
        // tail tile: per-edge path (32 lanes x float2)
        for (int i = 0; i < 16; i++) {
            int e = w * 16 + i;
            int ge = base + e;
            if (ge >= E) break;
            int s = __ldg(src + ge);
            int d = __ldg(dst + ge);
            float2 mv  = *(float2*)(Ms + (size_t)e * 68 + lane * 2);
            float2 npv = *(const float2*)(g_packed + (size_t)s * 128 + lane * 2);
            float v0 = mv.x + npv.x;
            float v1 = mv.y + npv.y;
            float mx = fmaxf(v0, v1);
#pragma unroll
            for (int o = 16; o > 0; o >>= 1) mx = fmaxf(mx, __shfl_xor_sync(0xffffffffu, mx, o));
            float e0 = __expf(v0 - mx);
            float e1 = __expf(v1 - mx);
            float ssum = e0 + e1;
#pragma unroll
            for (int o = 16; o > 0; o >>= 1) ssum += __shfl_xor_sync(0xffffffffu, ssum, o);
            float inv = 1.0f / ssum;
            float2 hv = *(const float2*)(g_packed + (size_t)s * 128 + 64 + lane * 2);
            float o0 = hv.x * e0 * inv;
            float o1 = hv.y * e1 * inv;
            float* addr = g_h_new + (size_t)d * 64 + lane * 2;
            asm volatile("red.global.add.v2.f32 [%0], {%1, %2};"
                         :: "l"(addr), "f"(o0), "f"(o1) : "memory");
        }
    }
}

// ---------------- GRU kernel: interleaved gates, register epilogue --------
// Warp w: rows (w&3)*16, interleaved-col half (w>>2). Each thread's even/odd
// n8-tile accumulator pair holds (r,z)/(gi,gh) of hidden j = half*32+m*4+(lane&3).
// No output staging: gate math in registers, scattered LDG/STG (L2-resident).
__global__ void gru_kernel(const float* __restrict__ hidden,
                           const float* __restrict__ b_ih,
                           const float* __restrict__ b_hh,
                           float* __restrict__ out, int N) {
    extern __shared__ __align__(16) char dsm[];
    char* As = dsm;                  // 64 x 256B
    char* Bs = dsm + 16384;          // 256 x 256B
    float* Bias = (float*)(dsm + 81920);  // [4][64]: B_r,B_z,B_i,B_h
    int t = threadIdx.x;
    int base = blockIdx.x * 64;

    if (t < 64) {
        Bias[t]       = b_ih[t]       + b_hh[t];        // r pre-act bias
        Bias[64 + t]  = b_ih[64 + t]  + b_hh[64 + t];   // z
        Bias[128 + t] = b_ih[128 + t];                  // gi_n
        Bias[192 + t] = b_hh[128 + t];                  // gh_n
    }

    // A load: STS.128 packed (8 floats per iter)
#pragma unroll
    for (int i = 0; i < 4; i++) {
        int idx = i * 256 + t;           // 1024 chunks of 8 floats
        int row = idx >> 4, c8 = idx & 15;
        int r = base + row; if (r >= N) r = N - 1;
        const float* p = (c8 < 8) ? (g_h_new + (size_t)r * 64 + c8 * 8)
                                  : (hidden  + (size_t)r * 64 + (c8 - 8) * 8);
        float4 v1 = *(const float4*)p;
        float4 v2 = *(const float4*)(p + 4);
        uint4 o;
        o.x = f2bf2(v1.x, v1.y); o.y = f2bf2(v1.z, v1.w);
        o.z = f2bf2(v2.x, v2.y); o.w = f2bf2(v2.z, v2.w);
        *(uint4*)(As + swz(row, c8)) = o;
    }
#pragma unroll
    for (int i = 0; i < 16; i++) ((uint4*)Bs)[i * 256 + t] = g_Wb_big[i * 256 + t];
    __syncthreads();

    int lane = t & 31, w = t >> 5;
    int mr = (w & 3) * 16;
    int halfw = w >> 2;               // 0..3 -> but only 2 col-halves; pairs share
    int ncb = (halfw & 1) * 128;      // warps 4-7 cover half 0/1 too (w>>2 in 0..1 for 8 warps? )
    // NOTE: 8 warps: (w&3)=row group, (w>>2)=0/1 col half. halfw in {0,1}.
    int qr = lane >> 2, qc = (lane & 3) * 4;
    int qq = lane & 3;
    float acc[16][4];
#pragma unroll
    for (int n = 0; n < 16; n++)
#pragma unroll
        for (int q = 0; q < 4; q++) acc[n][q] = 0.f;

#pragma unroll
    for (int k0 = 0; k0 < 128; k0 += 16) {
        int c0 = k0 >> 3, c1 = c0 + 1;
        unsigned a0 = *(unsigned*)(As + swz(mr + qr, c0) + qc);
        unsigned a1 = *(unsigned*)(As + swz(mr + qr + 8, c0) + qc);
        unsigned a2 = *(unsigned*)(As + swz(mr + qr, c1) + qc);
        unsigned a3 = *(unsigned*)(As + swz(mr + qr + 8, c1) + qc);
#pragma unroll
        for (int nt = 0; nt < 16; nt++) {
            unsigned b0 = *(unsigned*)(Bs + swz(ncb + nt * 8 + qr, c0) + qc);
            unsigned b1 = *(unsigned*)(Bs + swz(ncb + nt * 8 + qr, c1) + qc);
            mma16816(acc[nt], a0, a1, a2, a3, b0, b1);
        }
    }

    // register epilogue: per m, thread has (r,z) in acc[2m], (gi,gh) in acc[2m+1]
    int row0 = base + mr + qr;
    int row1 = row0 + 8;
#pragma unroll
    for (int m = 0; m < 8; m++) {
        int j = (ncb >> 2) + m * 4 + qq;     // half*32 + m*4 + qq
        float br = Bias[j], bz = Bias[64 + j];
        float bi = Bias[128 + j], bh = Bias[192 + j];
        // row0
        if (row0 < N) {
            float pr = acc[2 * m][0] + br;
            float pz = acc[2 * m][1] + bz;
            float pi = acc[2 * m + 1][0] + bi;
            float ph = acc[2 * m + 1][1] + bh;
            float r = 1.0f / (1.0f + __expf(-pr));
            float z = 1.0f / (1.0f + __expf(-pz));
            float ng = tanhf(fmaf(r, ph, pi));
            float h = __ldg(hidden + (size_t)row0 * 64 + j);
            out[(size_t)row0 * 64 + j] = fmaf(1.0f - z, ng, z * h);
        }
        // row1
        if (row1 < N) {
            float pr = acc[2 * m][2] + br;
            float pz = acc[2 * m][3] + bz;
            float pi = acc[2 * m + 1][2] + bi;
            float ph = acc[2 * m + 1][3] + bh;
            float r = 1.0f / (1.0f + __expf(-pr));
            float z = 1.0f / (1.0f + __expf(-pz));
            float ng = tanhf(fmaf(r, ph, pi));
            float h = __ldg(hidden + (size_t)row1 * 64 + j);
            out[(size_t)row1 * 64 + j] = fmaf(1.0f - z, ng, z * h);
        }
    }
}

// ---------------- launch --------------------------------------------------
extern "C" void kernel_launch(void* const* d_in, const int* in_sizes, int n_in,
                              void* d_out, int out_size) {
    const float* node_feats  = (const float*)d_in[0];
    const float* edge_feats  = (const float*)d_in[1];
    const float* node_hidden = (const float*)d_in[2];
    const int*   src         = (const int*)d_in[3];
    const int*   dst         = (const int*)d_in[4];
    const float* W_edge      = (const float*)d_in[5];
    const float* W_node      = (const float*)d_in[6];
    const float* W_ih        = (const float*)d_in[7];
    const float* W_hh        = (const float*)d_in[8];
    const float* b_ih        = (const float*)d_in[9];
    const float* b_hh        = (const float*)d_in[10];
    float* out = (float*)d_out;

    int E = in_sizes[3];
    int N = in_sizes[2] / HID;

    prep_kernel<<<24, 256>>>(W_edge, W_node, W_ih, W_hh);

    nodeproj_kernel<<<(N + 127) / 128, 256>>>(node_feats, node_hidden, N);

    edge_kernel<<<(E + 127) / 128, 256>>>(edge_feats, src, dst, E);

    static const int GRU_SMEM = 81920 + 1024;     // A+B + bias table
    cudaFuncSetAttribute(gru_kernel, cudaFuncAttributeMaxDynamicSharedMemorySize, GRU_SMEM);
    gru_kernel<<<(N + 63) / 64, 256, GRU_SMEM>>>(node_hidden, b_ih, b_hh, out, N);
}

// round 12
// speedup vs baseline: 1.2889x; 1.0050x over previous
#include <cuda_runtime.h>
#include <math.h>

#define HID 64
#define MAX_N 100000
#define MAX_E 1600000

// ---------------- device scratch (no allocations allowed) ----------------
// packed per-node gather row: [0:64)=node_proj, [64:128)=node_hidden (51.2MB)
__device__ float g_packed[MAX_N * 128];
__device__ float g_h_new[MAX_N * HID];       // 25.6 MB
// bf16 weight images, pre-swizzled into the smem tile layout:
// tile row stride 256B (128 bf16), 16B chunks, chunk c of row r stored at
// byte r*256 + ((c ^ (r&7))*16).
__device__ uint4 g_Wb_edge[64 * 16];         // W_edge  [j][k] bf16
__device__ uint4 g_Wb_node[64 * 16];         // W_node  [j][k] bf16
__device__ uint4 g_Wb_big[256 * 16];         // fused+interleaved GRU weights

// ---------------- helpers -------------------------------------------------
__device__ __forceinline__ unsigned f2bf2(float lo, float hi) {
    unsigned r;
    asm("cvt.rn.bf16x2.f32 %0, %1, %2;" : "=r"(r) : "f"(hi), "f"(lo));
    return r;
}

__device__ __forceinline__ int swz(int row, int chunk) {
    return row * 256 + ((chunk ^ (row & 7)) << 4);
}

__device__ __forceinline__ void mma16816(float c[4],
                                         unsigned a0, unsigned a1,
                                         unsigned a2, unsigned a3,
                                         unsigned b0, unsigned b1) {
    asm("mma.sync.aligned.m16n8k16.row.col.f32.bf16.bf16.f32 "
        "{%0,%1,%2,%3},{%4,%5,%6,%7},{%8,%9},{%0,%1,%2,%3};"
        : "+f"(c[0]), "+f"(c[1]), "+f"(c[2]), "+f"(c[3])
        : "r"(a0), "r"(a1), "r"(a2), "r"(a3), "r"(b0), "r"(b1));
}

// ---------------- weight prep: bf16 convert + swizzle + GRU fusion --------
// g_Wb_big column positions are INTERLEAVED so each thread's MMA accumulators
// hold all 4 gates of one hidden dim (see round-11 comment for decode).
__global__ void prep_kernel(const float* __restrict__ W_edge,
                            const float* __restrict__ W_node,
                            const float* __restrict__ W_ih,
                            const float* __restrict__ W_hh) {
    int idx = blockIdx.x * blockDim.x + threadIdx.x;  // one 16B chunk each
    float v[8];
    uint4* dst;
    if (idx < 1024) {
        int j = idx >> 4, c = idx & 15;
        const float* p = W_edge + j * 128 + c * 8;
#pragma unroll
        for (int i = 0; i < 8; i++) v[i] = p[i];
        dst = g_Wb_edge + (j * 16 + (c ^ (j & 7)));
    } else if (idx < 2048) {
        int i2 = idx - 1024;
        int j = i2 >> 4, c = i2 & 15;
        const float* p = W_node + j * 128 + c * 8;
#pragma unroll
        for (int i = 0; i < 8; i++) v[i] = p[i];
        dst = g_Wb_node + (j * 16 + (c ^ (j & 7)));
    } else if (idx < 6144) {
        int i3 = idx - 2048;
        int p = i3 >> 4, c = i3 & 15;
        int half = p >> 7, rem = p & 127;
        int nt = rem >> 3, m = nt >> 1, odd = nt & 1;
        int qq = (rem >> 1) & 3, par = rem & 1;
        int j = half * 32 + m * 4 + qq;
        int o = (odd ? (par ? 192 : 128) : (par ? 64 : 0)) + j;
#pragma unroll
        for (int i = 0; i < 8; i++) {
            int k = c * 8 + i;
            float val = 0.f;
            if (k < 64) {
                if (o < 192) val = W_ih[o * 64 + k];
            } else {
                int kk = k - 64;
                if (o < 128)       val = W_hh[o * 64 + kk];
                else if (o >= 192) val = W_hh[(o - 64) * 64 + kk];
            }
            v[i] = val;
        }
        dst = g_Wb_big + (p * 16 + (c ^ (p & 7)));
    } else {
        return;
    }
    uint4 o4;
    o4.x = f2bf2(v[0], v[1]);
    o4.y = f2bf2(v[2], v[3]);
    o4.z = f2bf2(v[4], v[5]);
    o4.w = f2bf2(v[6], v[7]);
    *dst = o4;
}

// ---------------- node_proj + pack hidden + zero h_new --------------------
__global__ void nodeproj_kernel(const float* __restrict__ nf,
                                const float* __restrict__ hidden, int N) {
    __shared__ __align__(16) char sm[49152];
    char* As = sm;                 // 128 x 256B bf16, swizzled
    char* Bs = sm + 32768;         // 64 x 256B bf16, swizzled
    float* Ms = (float*)sm;        // overlay [128][68] fp32 staging
    int t = threadIdx.x;
    int base = blockIdx.x * 128;

    // A load: one 16B bf16 chunk (8 floats = 2 float4) per iter -> STS.128
#pragma unroll
    for (int i = 0; i < 8; i++) {
        int idx = i * 256 + t;
        int row = idx >> 4, c8 = idx & 15;
        int r = base + row; if (r >= N) r = N - 1;
        const float4* p = (const float4*)(nf + (size_t)r * 128 + c8 * 8);
        float4 v1 = p[0], v2 = p[1];
        uint4 o;
        o.x = f2bf2(v1.x, v1.y); o.y = f2bf2(v1.z, v1.w);
        o.z = f2bf2(v2.x, v2.y); o.w = f2bf2(v2.z, v2.w);
        *(uint4*)(As + swz(row, c8)) = o;
    }
#pragma unroll
    for (int i = 0; i < 4; i++) ((uint4*)Bs)[i * 256 + t] = g_Wb_node[i * 256 + t];

    // hidden copy + h_new zero for this block's rows (independent of GEMM)
#pragma unroll
    for (int i = 0; i < 8; i++) {
        int idx = i * 256 + t;           // 2048 float4 chunks
        int row = idx >> 4, c4 = idx & 15;
        int r = base + row;
        if (r < N) {
            *(float4*)(g_packed + (size_t)r * 128 + 64 + c4 * 4) =
                *(const float4*)(hidden + (size_t)r * 64 + c4 * 4);
            *(float4*)(g_h_new + (size_t)r * 64 + c4 * 4) = make_float4(0.f, 0.f, 0.f, 0.f);
        }
    }
    __syncthreads();

    int lane = t & 31, w = t >> 5;
    int mr = w * 16;
    int qr = lane >> 2, qc = (lane & 3) * 4;
    float acc[8][4];
#pragma unroll
    for (int n = 0; n < 8; n++)
#pragma unroll
        for (int q = 0; q < 4; q++) acc[n][q] = 0.f;

#pragma unroll
    for (int k0 = 0; k0 < 128; k0 += 16) {
        int c0 = k0 >> 3, c1 = c0 + 1;
        unsigned a0 = *(unsigned*)(As + swz(mr + qr, c0) + qc);
        unsigned a1 = *(unsigned*)(As + swz(mr + qr + 8, c0) + qc);
        unsigned a2 = *(unsigned*)(As + swz(mr + qr, c1) + qc);
        unsigned a3 = *(unsigned*)(As + swz(mr + qr + 8, c1) + qc);
#pragma unroll
        for (int nt = 0; nt < 8; nt++) {
            unsigned b0 = *(unsigned*)(Bs + swz(nt * 8 + qr, c0) + qc);
            unsigned b1 = *(unsigned*)(Bs + swz(nt * 8 + qr, c1) + qc);
            mma16816(acc[nt], a0, a1, a2, a3, b0, b1);
        }
    }
    __syncthreads();
#pragma unroll
    for (int nt = 0; nt < 8; nt++) {
        int col = nt * 8 + (lane & 3) * 2;
        *(float2*)(Ms + (mr + qr) * 68 + col)     = make_float2(acc[nt][0], acc[nt][1]);
        *(float2*)(Ms + (mr + qr + 8) * 68 + col) = make_float2(acc[nt][2], acc[nt][3]);
    }
    __syncthreads();
#pragma unroll
    for (int i = 0; i < 8; i++) {
        int idx = i * 256 + t;
        int row = idx >> 4, c4 = idx & 15;
        int r = base + row;
        if (r < N)
            *(float4*)(g_packed + (size_t)r * 128 + c4 * 4) = *(float4*)(Ms + row * 68 + c4 * 4);
    }
}

// ---------------- fused edge kernel ---------------------------------------
// GEMM (proven) + REGISTER-EPILOGUE phase 2: each quad owns 2 edges' full
// 64-col rows in its accumulators; softmax = local reduce + 2 shfl rounds.
// No Ms staging, no post-GEMM syncthreads.
__global__ void __launch_bounds__(256, 4)
edge_kernel(const float* __restrict__ ef,
            const int* __restrict__ src,
            const int* __restrict__ dst,
            int E) {
    __shared__ __align__(16) char sm[49152];
    char* As = sm;                 // 128 x 256B bf16
    char* Bs = sm + 32768;         // 64 x 256B bf16
    int t = threadIdx.x;
    int lane = t & 31, w = t >> 5;
    int base = blockIdx.x * 128;
    int eclamp = E - 1;

    // ---- phase 0: L1-prefetch this warp's 16 gather rows (64 x 128B) ------
#pragma unroll
    for (int u = lane; u < 64; u += 32) {
        int ei = base + w * 16 + (u >> 2);
        if (ei > eclamp) ei = eclamp;
        int s = __ldg(src + ei);
        const char* gp = (const char*)(g_packed + (size_t)s * 128) + (u & 3) * 128;
        asm volatile("prefetch.global.L1 [%0];" :: "l"(gp));
    }

    // ---- phase 1: A tile load (streaming, STS.128 packed) + B copy --------
#pragma unroll
    for (int i = 0; i < 8; i++) {
        int idx = i * 256 + t;
        int row = idx >> 4, c8 = idx & 15;
        int r = base + row; if (r >= E) r = E - 1;
        const float4* p = (const float4*)(ef + (size_t)r * 128 + c8 * 8);
        float4 v1 = __ldcs(p), v2 = __ldcs(p + 1);
        uint4 o;
        o.x = f2bf2(v1.x, v1.y); o.y = f2bf2(v1.z, v1.w);
        o.z = f2bf2(v2.x, v2.y); o.w = f2bf2(v2.z, v2.w);
        *(uint4*)(As + swz(row, c8)) = o;
    }
#pragma unroll
    for (int i = 0; i < 4; i++) ((uint4*)Bs)[i * 256 + t] = g_Wb_edge[i * 256 + t];
    __syncthreads();

    // ---- GEMM (scalar fragment loads; proven) ------------------------------
    int mr = w * 16;
    int qr = lane >> 2, ql = lane & 3;
    int qc = ql * 4;
    float acc[8][4];
#pragma unroll
    for (int n = 0; n < 8; n++)
#pragma unroll
        for (int q = 0; q < 4; q++) acc[n][q] = 0.f;

#pragma unroll
    for (int k0 = 0; k0 < 128; k0 += 16) {
        int c0 = k0 >> 3, c1 = c0 + 1;
        unsigned a0 = *(unsigned*)(As + swz(mr + qr, c0) + qc);
        unsigned a1 = *(unsigned*)(As + swz(mr + qr + 8, c0) + qc);
        unsigned a2 = *(unsigned*)(As + swz(mr + qr, c1) + qc);
        unsigned a3 = *(unsigned*)(As + swz(mr + qr + 8, c1) + qc);
#pragma unroll
        for (int nt = 0; nt < 8; nt++) {
            unsigned b0 = *(unsigned*)(Bs + swz(nt * 8 + qr, c0) + qc);
            unsigned b1 = *(unsigned*)(Bs + swz(nt * 8 + qr, c1) + qc);
            mma16816(acc[nt], a0, a1, a2, a3, b0, b1);
        }
    }

    // ---- phase 2: register epilogue, quad-per-edge -------------------------
    // Quad (lanes 4*qr..4*qr+3) owns edges e0=w*16+qr (acc[nt][0,1]) and
    // e0+8 (acc[nt][2,3]); cols nt*8 + ql*2 + {0,1}.
    int ge0 = base + w * 16 + qr;
    int ge1 = ge0 + 8;
    int ce0 = min(ge0, eclamp), ce1 = min(ge1, eclamp);
    int s0 = __ldg(src + ce0), d0 = __ldg(dst + ce0);
    int s1 = __ldg(src + ce1), d1 = __ldg(dst + ce1);

#pragma unroll
    for (int rsel = 0; rsel < 2; rsel++) {
        int s = rsel ? s1 : s0;
        int d = rsel ? d1 : d0;
        int ge = rsel ? ge1 : ge0;
        int a0i = rsel * 2, a1i = rsel * 2 + 1;
        const float2* pp = (const float2*)(g_packed + (size_t)s * 128) + ql;
        const float2* hp = (const float2*)(g_packed + (size_t)s * 128 + 64) + ql;
        float vx[8], vy[8];
#pragma unroll
        for (int nt = 0; nt < 8; nt++) {
            float2 p = __ldg(pp + nt * 4);
            vx[nt] = acc[nt][a0i] + p.x;
            vy[nt] = acc[nt][a1i] + p.y;
        }
        float mx = fmaxf(vx[0], vy[0]);
#pragma unroll
        for (int nt = 1; nt < 8; nt++) mx = fmaxf(mx, fmaxf(vx[nt], vy[nt]));
        mx = fmaxf(mx, __shfl_xor_sync(0xffffffffu, mx, 1));
        mx = fmaxf(mx, __shfl_xor_sync(0xffffffffu, mx, 2));
        float ssum = 0.f;
#pragma unroll
        for (int nt = 0; nt < 8; nt++) {
            vx[nt] = __expf(vx[nt] - mx);
            vy[nt] = __expf(vy[nt] - mx);
            ssum += vx[nt] + vy[nt];
        }
        ssum += __shfl_xor_sync(0xffffffffu, ssum, 1);
        ssum += __shfl_xor_sync(0xffffffffu, ssum, 2);
        float inv = 1.0f / ssum;
        if (ge < E) {
            float* ob = g_h_new + (size_t)d * 64 + ql * 2;
#pragma unroll
            for (int nt = 0; nt < 8; nt++) {
                float2 h = __ldg(hp + nt * 4);
                float m0 = h.x * vx[nt] * inv;
                float m1 = h.y * vy[nt] * inv;
                asm volatile("red.global.add.v2.f32 [%0], {%1, %2};"
                             :: "l"(ob + nt * 8), "f"(m0), "f"(m1) : "memory");
            }
        }
    }
}

// ---------------- GRU kernel: interleaved gates, register epilogue --------
__global__ void gru_kernel(const float* __restrict__ hidden,
                           const float* __restrict__ b_ih,
                           const float* __restrict__ b_hh,
                           float* __restrict__ out, int N) {
    extern __shared__ __align__(16) char dsm[];
    char* As = dsm;                  // 64 x 256B
    char* Bs = dsm + 16384;          // 256 x 256B
    float* Bias = (float*)(dsm + 81920);  // [4][64]: B_r,B_z,B_i,B_h
    int t = threadIdx.x;
    int base = blockIdx.x * 64;

    if (t < 64) {
        Bias[t]       = b_ih[t]       + b_hh[t];        // r pre-act bias
        Bias[64 + t]  = b_ih[64 + t]  + b_hh[64 + t];   // z
        Bias[128 + t] = b_ih[128 + t];                  // gi_n
        Bias[192 + t] = b_hh[128 + t];                  // gh_n
    }

    // A load: STS.128 packed (8 floats per iter)
#pragma unroll
    for (int i = 0; i < 4; i++) {
        int idx = i * 256 + t;           // 1024 chunks of 8 floats
        int row = idx >> 4, c8 = idx & 15;
        int r = base + row; if (r >= N) r = N - 1;
        const float* p = (c8 < 8) ? (g_h_new + (size_t)r * 64 + c8 * 8)
                                  : (hidden  + (size_t)r * 64 + (c8 - 8) * 8);
        float4 v1 = *(const float4*)p;
        float4 v2 = *(const float4*)(p + 4);
        uint4 o;
        o.x = f2bf2(v1.x, v1.y); o.y = f2bf2(v1.z, v1.w);
        o.z = f2bf2(v2.x, v2.y); o.w = f2bf2(v2.z, v2.w);
        *(uint4*)(As + swz(row, c8)) = o;
    }
#pragma unroll
    for (int i = 0; i < 16; i++) ((uint4*)Bs)[i * 256 + t] = g_Wb_big[i * 256 + t];
    __syncthreads();

    int lane = t & 31, w = t >> 5;
    int mr = (w & 3) * 16;
    int ncb = ((w >> 2) & 1) * 128;   // 8 warps: (w&3)=rows, (w>>2)=col half
    int qr = lane >> 2, qc = (lane & 3) * 4;
    int qq = lane & 3;
    float acc[16][4];
#pragma unroll
    for (int n = 0; n < 16; n++)
#pragma unroll
        for (int q = 0; q < 4; q++) acc[n][q] = 0.f;

#pragma unroll
    for (int k0 = 0; k0 < 128; k0 += 16) {
        int c0 = k0 >> 3, c1 = c0 + 1;
        unsigned a0 = *(unsigned*)(As + swz(mr + qr, c0) + qc);
        unsigned a1 = *(unsigned*)(As + swz(mr + qr + 8, c0) + qc);
        unsigned a2 = *(unsigned*)(As + swz(mr + qr, c1) + qc);
        unsigned a3 = *(unsigned*)(As + swz(mr + qr + 8, c1) + qc);
#pragma unroll
        for (int nt = 0; nt < 16; nt++) {
            unsigned b0 = *(unsigned*)(Bs + swz(ncb + nt * 8 + qr, c0) + qc);
            unsigned b1 = *(unsigned*)(Bs + swz(ncb + nt * 8 + qr, c1) + qc);
            mma16816(acc[nt], a0, a1, a2, a3, b0, b1);
        }
    }

    // register epilogue: per m, thread has (r,z) in acc[2m], (gi,gh) in acc[2m+1]
    int row0 = base + mr + qr;
    int row1 = row0 + 8;
#pragma unroll
    for (int m = 0; m < 8; m++) {
        int j = (ncb >> 2) + m * 4 + qq;     // half*32 + m*4 + qq
        float br = Bias[j], bz = Bias[64 + j];
        float bi = Bias[128 + j], bh = Bias[192 + j];
        if (row0 < N) {
            float pr = acc[2 * m][0] + br;
            float pz = acc[2 * m][1] + bz;
            float pi = acc[2 * m + 1][0] + bi;
            float ph = acc[2 * m + 1][1] + bh;
            float r = 1.0f / (1.0f + __expf(-pr));
            float z = 1.0f / (1.0f + __expf(-pz));
            float ng = tanhf(fmaf(r, ph, pi));
            float h = __ldg(hidden + (size_t)row0 * 64 + j);
            out[(size_t)row0 * 64 + j] = fmaf(1.0f - z, ng, z * h);
        }
        if (row1 < N) {
            float pr = acc[2 * m][2] + br;
            float pz = acc[2 * m][3] + bz;
            float pi = acc[2 * m + 1][2] + bi;
            float ph = acc[2 * m + 1][3] + bh;
            float r = 1.0f / (1.0f + __expf(-pr));
            float z = 1.0f / (1.0f + __expf(-pz));
            float ng = tanhf(fmaf(r, ph, pi));
            float h = __ldg(hidden + (size_t)row1 * 64 + j);
            out[(size_t)row1 * 64 + j] = fmaf(1.0f - z, ng, z * h);
        }
    }
}

// ---------------- launch --------------------------------------------------
extern "C" void kernel_launch(void* const* d_in, const int* in_sizes, int n_in,
                              void* d_out, int out_size) {
    const float* node_feats  = (const float*)d_in[0];
    const float* edge_feats  = (const float*)d_in[1];
    const float* node_hidden = (const float*)d_in[2];
    const int*   src         = (const int*)d_in[3];
    const int*   dst         = (const int*)d_in[4];
    const float* W_edge      = (const float*)d_in[5];
    const float* W_node      = (const float*)d_in[6];
    const float* W_ih        = (const float*)d_in[7];
    const float* W_hh        = (const float*)d_in[8];
    const float* b_ih        = (const float*)d_in[9];
    const float* b_hh        = (const float*)d_in[10];
    float* out = (float*)d_out;

    int E = in_sizes[3];
    int N = in_sizes[2] / HID;

    prep_kernel<<<24, 256>>>(W_edge, W_node, W_ih, W_hh);

    nodeproj_kernel<<<(N + 127) / 128, 256>>>(node_feats, node_hidden, N);

    edge_kernel<<<(E + 127) / 128, 256>>>(edge_feats, src, dst, E);

    static const int GRU_SMEM = 81920 + 1024;     // A+B + bias table
    cudaFuncSetAttribute(gru_kernel, cudaFuncAttributeMaxDynamicSharedMemorySize, GRU_SMEM);
    gru_kernel<<<(N + 63) / 64, 256, GRU_SMEM>>>(node_hidden, b_ih, b_hh, out, N);
}